// round 10
// baseline (speedup 1.0000x reference)
#include <cuda_runtime.h>
#include <math.h>

#define NB 32
#define LL 1024
#define NI 600
#define NH 200
#define NR (NB*LL)

// ---------------- scratch (device globals; no runtime allocation) ----------
__device__ float g_t [NR*NH];                 // MLP layer1 temp
__device__ float g_h1[NR*NH];                 // mlp(s1)
__device__ float g_h2[NR*NH];                 // mlp(s2)
__device__ float g_e [(size_t)NB*LL*LL];      // e, then in-place exp for beta
__device__ float g_ea[(size_t)NB*LL*LL];      // un-normalized exp for alpha
__device__ float g_ia[NR];                    // 1/sum per (b,m) for alpha
__device__ float g_ib[NR];                    // 1/sum per (b,l) for beta

// ---------------- packed f32x2 helpers (sm_100+) ---------------------------
__device__ __forceinline__ unsigned long long pack2(float x) {
    unsigned long long r;
    asm("mov.b64 %0, {%1, %1};" : "=l"(r) : "f"(x));
    return r;
}
__device__ __forceinline__ void fma2(unsigned long long& d,
                                     unsigned long long a,
                                     unsigned long long b) {
    asm("fma.rn.f32x2 %0, %1, %2, %3;" : "=l"(d) : "l"(a), "l"(b), "l"(d));
}
__device__ __forceinline__ float2 unpack2(unsigned long long v) {
    float2 f;
    asm("mov.b64 {%0, %1}, %2;" : "=f"(f.x), "=f"(f.y) : "l"(v));
    return f;
}

// ---------------------------------------------------------------------------
// Unified 128x128x8 SGEMM, 256 threads, 8x8 micro-tile (as 8x4 f32x2 pairs),
// register prefetch, packed fma.rn.f32x2 inner product.
//   EPI: 0 = plain store, 1 = relu(acc + P1[c]), 2 = acc * P1[b*LL+r]*P2[b*LL+r]
//   ATR: A global is [M][K] (k-contiguous, transpose on smem store)
//        else A is [K][M] (m-contiguous, direct smem store)
//   BTR: B global is [N][K] (transpose on store) else [K][N] direct
//   NG : N needs bounds guards (N not multiple of 128)
// Requirements: M % 128 == 0, K % 8 == 0 (true for all shapes here).
// ---------------------------------------------------------------------------
template<int EPI, bool ATR, bool BTR, bool NG>
__global__ __launch_bounds__(256, 2)
void gemm128(const float* __restrict__ Ag, const float* __restrict__ Bg,
             const float* __restrict__ P1, const float* __restrict__ P2,
             float* __restrict__ Cg,
             int N, int K, int lda, int ldb, int ldc,
             size_t sA, size_t sB, size_t sC)
{
    const int b = blockIdx.z;
    const float* A = Ag + (size_t)b * sA;
    const float* B = Bg + (size_t)b * sB;
    float*       C = Cg + (size_t)b * sC;

    __shared__ __align__(16) float As[8][132];
    __shared__ __align__(16) float Bs[8][132];

    const int tid  = threadIdx.x;
    const int tx   = tid & 15;           // 0..15 col group
    const int ty   = tid >> 4;           // 0..15 row group
    const int row0 = blockIdx.y * 128;
    const int col0 = blockIdx.x * 128;

    // load-index precompute
    const int t2r  = tid >> 1;           // 0..127 (transpose loads)
    const int t2k  = (tid & 1) * 4;      // 0 or 4
    const int t32k = tid >> 5;           // 0..7   (direct loads)
    const int t32c = (tid & 31) * 4;     // 0..124

    // acc2[i][jp] holds output columns (jp*2, jp*2+1) of micro-column block
    unsigned long long acc2[8][4] = {};
    float4 ra, rb;

    auto loadA = [&](int k0) {
        if (ATR) {
            ra = *reinterpret_cast<const float4*>(&A[(size_t)(row0 + t2r) * lda + k0 + t2k]);
        } else {
            ra = *reinterpret_cast<const float4*>(&A[(size_t)(k0 + t32k) * lda + row0 + t32c]);
        }
    };
    auto loadB = [&](int k0) {
        if (BTR) {
            rb = *reinterpret_cast<const float4*>(&B[(size_t)(col0 + t2r) * ldb + k0 + t2k]);
        } else {
            int gc = col0 + t32c;
            const float* p = &B[(size_t)(k0 + t32k) * ldb + gc];
            if (!NG || gc + 3 < N) {
                rb = *reinterpret_cast<const float4*>(p);
            } else {
                rb.x = (gc + 0 < N) ? p[0] : 0.f;
                rb.y = (gc + 1 < N) ? p[1] : 0.f;
                rb.z = (gc + 2 < N) ? p[2] : 0.f;
                rb.w = (gc + 3 < N) ? p[3] : 0.f;
            }
        }
    };
    auto storeA = [&]() {
        if (ATR) {
            As[t2k + 0][t2r] = ra.x; As[t2k + 1][t2r] = ra.y;
            As[t2k + 2][t2r] = ra.z; As[t2k + 3][t2r] = ra.w;
        } else {
            *reinterpret_cast<float4*>(&As[t32k][t32c]) = ra;
        }
    };
    auto storeB = [&]() {
        if (BTR) {
            Bs[t2k + 0][t2r] = rb.x; Bs[t2k + 1][t2r] = rb.y;
            Bs[t2k + 2][t2r] = rb.z; Bs[t2k + 3][t2r] = rb.w;
        } else {
            *reinterpret_cast<float4*>(&Bs[t32k][t32c]) = rb;
        }
    };

    loadA(0); loadB(0);
    for (int k0 = 0; k0 < K; k0 += 8) {
        storeA(); storeB();
        __syncthreads();
        if (k0 + 8 < K) { loadA(k0 + 8); loadB(k0 + 8); }   // prefetch next tile
        #pragma unroll
        for (int kk = 0; kk < 8; kk++) {
            float4 a0 = *reinterpret_cast<const float4*>(&As[kk][ty * 4]);
            float4 a1 = *reinterpret_cast<const float4*>(&As[kk][64 + ty * 4]);
            // B fragments as natural f32x2 pairs straight from smem (16B aligned)
            ulonglong2 bq0 = *reinterpret_cast<const ulonglong2*>(&Bs[kk][tx * 4]);
            ulonglong2 bq1 = *reinterpret_cast<const ulonglong2*>(&Bs[kk][64 + tx * 4]);
            unsigned long long bv[4] = {bq0.x, bq0.y, bq1.x, bq1.y};
            float av[8] = {a0.x, a0.y, a0.z, a0.w, a1.x, a1.y, a1.z, a1.w};
            #pragma unroll
            for (int i = 0; i < 8; i++) {
                unsigned long long a2 = pack2(av[i]);
                #pragma unroll
                for (int jp = 0; jp < 4; jp++)
                    fma2(acc2[i][jp], a2, bv[jp]);
            }
        }
        __syncthreads();
    }

    #pragma unroll
    for (int ri = 0; ri < 2; ri++) {
        #pragma unroll
        for (int i = 0; i < 4; i++) {
            int r = row0 + ri * 64 + ty * 4 + i;
            float scale = 1.f;
            if (EPI == 2) scale = P1[b * LL + r] * P2[b * LL + r];
            #pragma unroll
            for (int ci = 0; ci < 2; ci++) {
                #pragma unroll
                for (int jp = 0; jp < 2; jp++) {
                    float2 v2 = unpack2(acc2[ri * 4 + i][ci * 2 + jp]);
                    int c = col0 + ci * 64 + tx * 4 + jp * 2;
                    float v0 = v2.x, v1 = v2.y;
                    if (EPI == 1) {
                        if (!NG || c + 0 < N) v0 = fmaxf(v0 + P1[c + 0], 0.f);
                        if (!NG || c + 1 < N) v1 = fmaxf(v1 + P1[c + 1], 0.f);
                    }
                    if (EPI == 2) { v0 *= scale; v1 *= scale; }
                    if (!NG || c + 0 < N) C[(size_t)r * ldc + c + 0] = v0;
                    if (!NG || c + 1 < N) C[(size_t)r * ldc + c + 1] = v1;
                }
            }
        }
    }
}

// ---------------------------------------------------------------------------
// Alpha softmax (over l, per column m): UN-normalized exp into g_ea, 1/sum
// into g_ia.  logit[l,m] = e[l,m] * mask1[b,l]
// ---------------------------------------------------------------------------
__global__ __launch_bounds__(256)
void k_softmax_cols(const float* __restrict__ mask1) {
    int b = blockIdx.y;
    int m = blockIdx.x * 256 + threadIdx.x;
    const float* pe = g_e  + (size_t)b*LL*LL + m;
    float*       po = g_ea + (size_t)b*LL*LL + m;
    __shared__ float smk[LL];
    for (int l = threadIdx.x; l < LL; l += 256) smk[l] = mask1[b*LL + l];
    __syncthreads();
    float mx = -3.4e38f;
    for (int l = 0; l < LL; l++) {
        float v = pe[(size_t)l*LL] * smk[l];
        mx = fmaxf(mx, v);
    }
    float s = 0.f;
    for (int l = 0; l < LL; l++) {
        float t = __expf(pe[(size_t)l*LL] * smk[l] - mx);
        po[(size_t)l*LL] = t;
        s += t;
    }
    g_ia[b*LL + m] = 1.f / s;
}

// ---------------------------------------------------------------------------
// Beta softmax (over m, per row l): IN-PLACE on g_e, 1/sum into g_ib.
// ---------------------------------------------------------------------------
__global__ __launch_bounds__(256)
void k_softmax_rows(const float* __restrict__ mask2) {
    int row = blockIdx.x;        // b*LL + l
    int b = row >> 10;
    float* p = g_e + (size_t)row*LL;
    const float* mk = mask2 + b*LL;
    int tid = threadIdx.x;
    __shared__ float red[256];
    float v[4];
    float mx = -3.4e38f;
    #pragma unroll
    for (int i = 0; i < 4; i++) {
        int m = tid + i*256;
        v[i] = p[m] * mk[m];
        mx = fmaxf(mx, v[i]);
    }
    red[tid] = mx; __syncthreads();
    for (int s = 128; s > 0; s >>= 1) {
        if (tid < s) red[tid] = fmaxf(red[tid], red[tid + s]);
        __syncthreads();
    }
    mx = red[0]; __syncthreads();
    float sum = 0.f;
    #pragma unroll
    for (int i = 0; i < 4; i++) { v[i] = __expf(v[i] - mx); sum += v[i]; }
    red[tid] = sum; __syncthreads();
    for (int s = 128; s > 0; s >>= 1) {
        if (tid < s) red[tid] += red[tid + s];
        __syncthreads();
    }
    float total = red[0];
    #pragma unroll
    for (int i = 0; i < 4; i++) p[tid + i*256] = v[i];
    if (tid == 0) g_ib[row] = 1.f / total;
}

// ---------------------------------------------------------------------------
extern "C" void kernel_launch(void* const* d_in, const int* in_sizes, int n_in,
                              void* d_out, int out_size) {
    const float* s1    = (const float*)d_in[0];
    const float* s2    = (const float*)d_in[1];
    const float* mask1 = (const float*)d_in[2];
    const float* mask2 = (const float*)d_in[3];
    const float* W1    = (const float*)d_in[4];
    const float* b1    = (const float*)d_in[5];
    const float* W2    = (const float*)d_in[6];
    const float* b2    = (const float*)d_in[7];
    float* out       = (float*)d_out;
    float* out_alpha = out;
    float* out_beta  = out + (size_t)NB*LL*NI;

    float *p_t, *p_h1, *p_h2, *p_e, *p_ea, *p_ia, *p_ib;
    cudaGetSymbolAddress((void**)&p_t,  g_t);
    cudaGetSymbolAddress((void**)&p_h1, g_h1);
    cudaGetSymbolAddress((void**)&p_h2, g_h2);
    cudaGetSymbolAddress((void**)&p_e,  g_e);
    cudaGetSymbolAddress((void**)&p_ea, g_ea);
    cudaGetSymbolAddress((void**)&p_ia, g_ia);
    cudaGetSymbolAddress((void**)&p_ib, g_ib);

    dim3 blk(256);

    // ---- MLP: h = relu(relu(x@W1+b1)@W2+b2) for both streams -------------
    // M=32768 (mult of 128), N=200 (guarded), K=600/200 (mult of 8)
    {
        dim3 g1((NH + 127) / 128, NR / 128, 1);   // (2, 256)
        gemm128<1,true,false,true><<<g1, blk>>>(s1,  W1, b1, nullptr, p_t,
                                                NH, NI, NI, NH, NH, 0, 0, 0);
        gemm128<1,true,false,true><<<g1, blk>>>(p_t, W2, b2, nullptr, p_h1,
                                                NH, NH, NH, NH, NH, 0, 0, 0);
        gemm128<1,true,false,true><<<g1, blk>>>(s2,  W1, b1, nullptr, p_t,
                                                NH, NI, NI, NH, NH, 0, 0, 0);
        gemm128<1,true,false,true><<<g1, blk>>>(p_t, W2, b2, nullptr, p_h2,
                                                NH, NH, NH, NH, NH, 0, 0, 0);
    }

    // ---- e[b,l,m] = h1 @ h2^T : NT, M=N=1024, K=200 -----------------------
    {
        dim3 ge(LL / 128, LL / 128, NB);          // (8, 8, 32)
        gemm128<0,true,true,false><<<ge, blk>>>(p_h1, p_h2, nullptr, nullptr, p_e,
                                                LL, NH, NH, NH, LL,
                                                (size_t)LL*NH, (size_t)LL*NH, (size_t)LL*LL);
    }

    // ---- softmaxes (alpha first: beta overwrites g_e in place) ------------
    {
        dim3 gs(LL / 256, NB);
        k_softmax_cols<<<gs, blk>>>(mask1);
    }
    k_softmax_rows<<<NR, blk>>>(mask2);

    // ---- alphas (TN) and betas (NN): M=1024, N=600, K=1024 ----------------
    {
        dim3 ga((NI + 127) / 128, LL / 128, NB);  // (5, 8, 32)
        // alphas[b,m,d] = (inv_a*mask2)[b,m] * sum_l ea[b,l,m] * s1[b,l,d]
        gemm128<2,false,false,true><<<ga, blk>>>(p_ea, s1, p_ia, mask2, out_alpha,
                                                 NI, LL, LL, NI, NI,
                                                 (size_t)LL*LL, (size_t)LL*NI, (size_t)LL*NI);
        // betas[b,l,d] = (inv_b*mask1)[b,l] * sum_m e[b,l,m] * s2[b,m,d]
        gemm128<2,true,false,true><<<ga, blk>>>(p_e, s2, p_ib, mask1, out_beta,
                                                NI, LL, LL, NI, NI,
                                                (size_t)LL*LL, (size_t)LL*NI, (size_t)LL*NI);
    }
}

// round 11
// speedup vs baseline: 1.0053x; 1.0053x over previous
#include <cuda_runtime.h>
#include <math.h>

#define NB 32
#define LL 1024
#define NI 600
#define NH 200
#define NR (NB*LL)

// ---------------- scratch (device globals; no runtime allocation) ----------
__device__ float g_t [NR*NH];                 // MLP layer1 temp
__device__ float g_h1[NR*NH];                 // mlp(s1)
__device__ float g_h2[NR*NH];                 // mlp(s2)
__device__ float g_e [(size_t)NB*LL*LL];      // e, then in-place exp for beta
__device__ float g_ea[(size_t)NB*LL*LL];      // un-normalized exp for alpha
__device__ float g_ia[NR];                    // 1/sum per (b,m) for alpha
__device__ float g_ib[NR];                    // 1/sum per (b,l) for beta

// ---------------- packed f32x2 helpers (sm_100+) ---------------------------
__device__ __forceinline__ unsigned long long pack2(float x) {
    unsigned long long r;
    asm("mov.b64 %0, {%1, %1};" : "=l"(r) : "f"(x));
    return r;
}
__device__ __forceinline__ void fma2(unsigned long long& d,
                                     unsigned long long a,
                                     unsigned long long b) {
    asm("fma.rn.f32x2 %0, %1, %2, %3;" : "=l"(d) : "l"(a), "l"(b), "l"(d));
}
__device__ __forceinline__ float2 unpack2(unsigned long long v) {
    float2 f;
    asm("mov.b64 {%0, %1}, %2;" : "=f"(f.x), "=f"(f.y) : "l"(v));
    return f;
}

// ---------------------------------------------------------------------------
// Unified 128x128x8 SGEMM, 256 threads, 8x8 micro-tile (as 8x4 f32x2 pairs),
// register prefetch, packed fma.rn.f32x2 inner product.
//   EPI: 0 = plain store, 1 = relu(acc + P1[c]), 2 = acc * P1[b*LL+r]*P2[b*LL+r]
//   ATR: A global is [M][K] (k-contiguous, transpose on smem store)
//        else A is [K][M] (m-contiguous, direct smem store)
//   BTR: B global is [N][K] (transpose on store) else [K][N] direct
//   NG : N needs bounds guards (N not multiple of 128)
// Requirements: M % 128 == 0, K % 8 == 0 (true for all shapes here).
// ---------------------------------------------------------------------------
template<int EPI, bool ATR, bool BTR, bool NG>
__global__ __launch_bounds__(256, 2)
void gemm128(const float* __restrict__ Ag, const float* __restrict__ Bg,
             const float* __restrict__ P1, const float* __restrict__ P2,
             float* __restrict__ Cg,
             int N, int K, int lda, int ldb, int ldc,
             size_t sA, size_t sB, size_t sC)
{
    const int b = blockIdx.z;
    const float* A = Ag + (size_t)b * sA;
    const float* B = Bg + (size_t)b * sB;
    float*       C = Cg + (size_t)b * sC;

    __shared__ __align__(16) float As[8][132];
    __shared__ __align__(16) float Bs[8][132];

    const int tid  = threadIdx.x;
    const int tx   = tid & 15;           // 0..15 col group
    const int ty   = tid >> 4;           // 0..15 row group
    const int row0 = blockIdx.y * 128;
    const int col0 = blockIdx.x * 128;

    // load-index precompute
    const int t2r  = tid >> 1;           // 0..127 (transpose loads)
    const int t2k  = (tid & 1) * 4;      // 0 or 4
    const int t32k = tid >> 5;           // 0..7   (direct loads)
    const int t32c = (tid & 31) * 4;     // 0..124

    // acc2[i][jp] holds output columns (jp*2, jp*2+1) of micro-column block
    unsigned long long acc2[8][4] = {};
    float4 ra, rb;

    auto loadA = [&](int k0) {
        if (ATR) {
            ra = *reinterpret_cast<const float4*>(&A[(size_t)(row0 + t2r) * lda + k0 + t2k]);
        } else {
            ra = *reinterpret_cast<const float4*>(&A[(size_t)(k0 + t32k) * lda + row0 + t32c]);
        }
    };
    auto loadB = [&](int k0) {
        if (BTR) {
            rb = *reinterpret_cast<const float4*>(&B[(size_t)(col0 + t2r) * ldb + k0 + t2k]);
        } else {
            int gc = col0 + t32c;
            const float* p = &B[(size_t)(k0 + t32k) * ldb + gc];
            if (!NG || gc + 3 < N) {
                rb = *reinterpret_cast<const float4*>(p);
            } else {
                rb.x = (gc + 0 < N) ? p[0] : 0.f;
                rb.y = (gc + 1 < N) ? p[1] : 0.f;
                rb.z = (gc + 2 < N) ? p[2] : 0.f;
                rb.w = (gc + 3 < N) ? p[3] : 0.f;
            }
        }
    };
    auto storeA = [&]() {
        if (ATR) {
            As[t2k + 0][t2r] = ra.x; As[t2k + 1][t2r] = ra.y;
            As[t2k + 2][t2r] = ra.z; As[t2k + 3][t2r] = ra.w;
        } else {
            *reinterpret_cast<float4*>(&As[t32k][t32c]) = ra;
        }
    };
    auto storeB = [&]() {
        if (BTR) {
            Bs[t2k + 0][t2r] = rb.x; Bs[t2k + 1][t2r] = rb.y;
            Bs[t2k + 2][t2r] = rb.z; Bs[t2k + 3][t2r] = rb.w;
        } else {
            *reinterpret_cast<float4*>(&Bs[t32k][t32c]) = rb;
        }
    };

    loadA(0); loadB(0);
    for (int k0 = 0; k0 < K; k0 += 8) {
        storeA(); storeB();
        __syncthreads();
        if (k0 + 8 < K) { loadA(k0 + 8); loadB(k0 + 8); }   // prefetch next tile
        #pragma unroll
        for (int kk = 0; kk < 8; kk++) {
            float4 a0 = *reinterpret_cast<const float4*>(&As[kk][ty * 4]);
            float4 a1 = *reinterpret_cast<const float4*>(&As[kk][64 + ty * 4]);
            // B fragments as natural f32x2 pairs straight from smem (16B aligned)
            ulonglong2 bq0 = *reinterpret_cast<const ulonglong2*>(&Bs[kk][tx * 4]);
            ulonglong2 bq1 = *reinterpret_cast<const ulonglong2*>(&Bs[kk][64 + tx * 4]);
            unsigned long long bv[4] = {bq0.x, bq0.y, bq1.x, bq1.y};
            float av[8] = {a0.x, a0.y, a0.z, a0.w, a1.x, a1.y, a1.z, a1.w};
            #pragma unroll
            for (int i = 0; i < 8; i++) {
                unsigned long long a2 = pack2(av[i]);
                #pragma unroll
                for (int jp = 0; jp < 4; jp++)
                    fma2(acc2[i][jp], a2, bv[jp]);
            }
        }
        __syncthreads();
    }

    #pragma unroll
    for (int ri = 0; ri < 2; ri++) {
        #pragma unroll
        for (int i = 0; i < 4; i++) {
            int r = row0 + ri * 64 + ty * 4 + i;
            float scale = 1.f;
            if (EPI == 2) scale = P1[b * LL + r] * P2[b * LL + r];
            #pragma unroll
            for (int ci = 0; ci < 2; ci++) {
                #pragma unroll
                for (int jp = 0; jp < 2; jp++) {
                    float2 v2 = unpack2(acc2[ri * 4 + i][ci * 2 + jp]);
                    int c = col0 + ci * 64 + tx * 4 + jp * 2;
                    float v0 = v2.x, v1 = v2.y;
                    if (EPI == 1) {
                        if (!NG || c + 0 < N) v0 = fmaxf(v0 + P1[c + 0], 0.f);
                        if (!NG || c + 1 < N) v1 = fmaxf(v1 + P1[c + 1], 0.f);
                    }
                    if (EPI == 2) { v0 *= scale; v1 *= scale; }
                    if (!NG || c + 0 < N) C[(size_t)r * ldc + c + 0] = v0;
                    if (!NG || c + 1 < N) C[(size_t)r * ldc + c + 1] = v1;
                }
            }
        }
    }
}

// ---------------------------------------------------------------------------
// Alpha softmax (over l, per column m): UN-normalized exp into g_ea, 1/sum
// into g_ia.  logit[l,m] = e[l,m] * mask1[b,l]
// ---------------------------------------------------------------------------
__global__ __launch_bounds__(256)
void k_softmax_cols(const float* __restrict__ mask1) {
    int b = blockIdx.y;
    int m = blockIdx.x * 256 + threadIdx.x;
    const float* pe = g_e  + (size_t)b*LL*LL + m;
    float*       po = g_ea + (size_t)b*LL*LL + m;
    __shared__ float smk[LL];
    for (int l = threadIdx.x; l < LL; l += 256) smk[l] = mask1[b*LL + l];
    __syncthreads();
    float mx = -3.4e38f;
    for (int l = 0; l < LL; l++) {
        float v = pe[(size_t)l*LL] * smk[l];
        mx = fmaxf(mx, v);
    }
    float s = 0.f;
    for (int l = 0; l < LL; l++) {
        float t = __expf(pe[(size_t)l*LL] * smk[l] - mx);
        po[(size_t)l*LL] = t;
        s += t;
    }
    g_ia[b*LL + m] = 1.f / s;
}

// ---------------------------------------------------------------------------
// Beta softmax (over m, per row l): IN-PLACE on g_e, 1/sum into g_ib.
// ---------------------------------------------------------------------------
__global__ __launch_bounds__(256)
void k_softmax_rows(const float* __restrict__ mask2) {
    int row = blockIdx.x;        // b*LL + l
    int b = row >> 10;
    float* p = g_e + (size_t)row*LL;
    const float* mk = mask2 + b*LL;
    int tid = threadIdx.x;
    __shared__ float red[256];
    float v[4];
    float mx = -3.4e38f;
    #pragma unroll
    for (int i = 0; i < 4; i++) {
        int m = tid + i*256;
        v[i] = p[m] * mk[m];
        mx = fmaxf(mx, v[i]);
    }
    red[tid] = mx; __syncthreads();
    for (int s = 128; s > 0; s >>= 1) {
        if (tid < s) red[tid] = fmaxf(red[tid], red[tid + s]);
        __syncthreads();
    }
    mx = red[0]; __syncthreads();
    float sum = 0.f;
    #pragma unroll
    for (int i = 0; i < 4; i++) { v[i] = __expf(v[i] - mx); sum += v[i]; }
    red[tid] = sum; __syncthreads();
    for (int s = 128; s > 0; s >>= 1) {
        if (tid < s) red[tid] += red[tid + s];
        __syncthreads();
    }
    float total = red[0];
    #pragma unroll
    for (int i = 0; i < 4; i++) p[tid + i*256] = v[i];
    if (tid == 0) g_ib[row] = 1.f / total;
}

// ---------------------------------------------------------------------------
extern "C" void kernel_launch(void* const* d_in, const int* in_sizes, int n_in,
                              void* d_out, int out_size) {
    const float* s1    = (const float*)d_in[0];
    const float* s2    = (const float*)d_in[1];
    const float* mask1 = (const float*)d_in[2];
    const float* mask2 = (const float*)d_in[3];
    const float* W1    = (const float*)d_in[4];
    const float* b1    = (const float*)d_in[5];
    const float* W2    = (const float*)d_in[6];
    const float* b2    = (const float*)d_in[7];
    float* out       = (float*)d_out;
    float* out_alpha = out;
    float* out_beta  = out + (size_t)NB*LL*NI;

    float *p_t, *p_h1, *p_h2, *p_e, *p_ea, *p_ia, *p_ib;
    cudaGetSymbolAddress((void**)&p_t,  g_t);
    cudaGetSymbolAddress((void**)&p_h1, g_h1);
    cudaGetSymbolAddress((void**)&p_h2, g_h2);
    cudaGetSymbolAddress((void**)&p_e,  g_e);
    cudaGetSymbolAddress((void**)&p_ea, g_ea);
    cudaGetSymbolAddress((void**)&p_ia, g_ia);
    cudaGetSymbolAddress((void**)&p_ib, g_ib);

    dim3 blk(256);

    // ---- MLP: h = relu(relu(x@W1+b1)@W2+b2) for both streams -------------
    // M=32768 (mult of 128), N=200 (guarded), K=600/200 (mult of 8)
    {
        dim3 g1((NH + 127) / 128, NR / 128, 1);   // (2, 256)
        gemm128<1,true,false,true><<<g1, blk>>>(s1,  W1, b1, nullptr, p_t,
                                                NH, NI, NI, NH, NH, 0, 0, 0);
        gemm128<1,true,false,true><<<g1, blk>>>(p_t, W2, b2, nullptr, p_h1,
                                                NH, NH, NH, NH, NH, 0, 0, 0);
        gemm128<1,true,false,true><<<g1, blk>>>(s2,  W1, b1, nullptr, p_t,
                                                NH, NI, NI, NH, NH, 0, 0, 0);
        gemm128<1,true,false,true><<<g1, blk>>>(p_t, W2, b2, nullptr, p_h2,
                                                NH, NH, NH, NH, NH, 0, 0, 0);
    }

    // ---- e[b,l,m] = h1 @ h2^T : NT, M=N=1024, K=200 -----------------------
    {
        dim3 ge(LL / 128, LL / 128, NB);          // (8, 8, 32)
        gemm128<0,true,true,false><<<ge, blk>>>(p_h1, p_h2, nullptr, nullptr, p_e,
                                                LL, NH, NH, NH, LL,
                                                (size_t)LL*NH, (size_t)LL*NH, (size_t)LL*LL);
    }

    // ---- softmaxes (alpha first: beta overwrites g_e in place) ------------
    {
        dim3 gs(LL / 256, NB);
        k_softmax_cols<<<gs, blk>>>(mask1);
    }
    k_softmax_rows<<<NR, blk>>>(mask2);

    // ---- alphas (TN) and betas (NN): M=1024, N=600, K=1024 ----------------
    {
        dim3 ga((NI + 127) / 128, LL / 128, NB);  // (5, 8, 32)
        // alphas[b,m,d] = (inv_a*mask2)[b,m] * sum_l ea[b,l,m] * s1[b,l,d]
        gemm128<2,false,false,true><<<ga, blk>>>(p_ea, s1, p_ia, mask2, out_alpha,
                                                 NI, LL, LL, NI, NI,
                                                 (size_t)LL*LL, (size_t)LL*NI, (size_t)LL*NI);
        // betas[b,l,d] = (inv_b*mask1)[b,l] * sum_m e[b,l,m] * s2[b,m,d]
        gemm128<2,true,false,true><<<ga, blk>>>(p_e, s2, p_ib, mask1, out_beta,
                                                NI, LL, LL, NI, NI,
                                                (size_t)LL*LL, (size_t)LL*NI, (size_t)LL*NI);
    }
}

// round 12
// speedup vs baseline: 1.0349x; 1.0295x over previous
#include <cuda_runtime.h>
#include <math.h>

#define NB 32
#define LL 1024
#define NI 600
#define NH 200
#define NR (NB*LL)

// ---------------- scratch (device globals; no runtime allocation) ----------
__device__ float g_t [NR*NH];                 // MLP layer1 temp
__device__ float g_h1[NR*NH];                 // mlp(s1)
__device__ float g_h2[NR*NH];                 // mlp(s2)
__device__ float g_e [(size_t)NB*LL*LL];      // e, then in-place exp for beta
__device__ float g_ea[(size_t)NB*LL*LL];      // un-normalized exp for alpha
__device__ float g_ia[NR];                    // 1/sum per (b,m) for alpha
__device__ float g_ib[NR];                    // 1/sum per (b,l) for beta

// ---------------------------------------------------------------------------
// Unified 128x128x16 SGEMM, 256 threads, 8x8 micro-tile, double-buffered smem
// (ONE __syncthreads per K-iter), register prefetch, scalar FFMA.
//   EPI: 0 = plain store, 1 = relu(acc + P1[c]), 2 = acc * P1[b*LL+r]*P2[b*LL+r]
//   ATR: A global is [M][K] (k-contiguous, transpose on smem store)
//        else A is [K][M] (m-contiguous, direct smem store)
//   BTR: B global is [N][K] (transpose on store) else [K][N] direct
//   NG : B/N needs bounds guards (N not multiple of 128)
// Requirements: M % 128 == 0, K % 8 == 0 (K%16 handled via zero-fill tail).
// ---------------------------------------------------------------------------
template<int EPI, bool ATR, bool BTR, bool NG>
__global__ __launch_bounds__(256, 2)
void gemm128(const float* __restrict__ Ag, const float* __restrict__ Bg,
             const float* __restrict__ P1, const float* __restrict__ P2,
             float* __restrict__ Cg,
             int N, int K, int lda, int ldb, int ldc,
             size_t sA, size_t sB, size_t sC)
{
    const int b = blockIdx.z;
    const float* A = Ag + (size_t)b * sA;
    const float* B = Bg + (size_t)b * sB;
    float*       C = Cg + (size_t)b * sC;

    __shared__ __align__(16) float As[2][16][132];
    __shared__ __align__(16) float Bs[2][16][132];

    const int tid  = threadIdx.x;
    const int tx   = tid & 15;           // 0..15 col group
    const int ty   = tid >> 4;           // 0..15 row group
    const int row0 = blockIdx.y * 128;
    const int col0 = blockIdx.x * 128;

    // transpose-load mapping ([R][K] sources): 2 threads/row, chunks {trk, trk+8}
    const int trr = tid >> 1;            // 0..127
    const int trk = (tid & 1) * 4;       // 0 or 4
    // direct-load mapping ([K][C] sources): 16 threads/row, 8 floats each
    const int dk  = tid >> 4;            // 0..15
    const int dc  = (tid & 15) * 8;      // 0..120

    float acc[8][8] = {};
    float4 pa0, pa1, pb0, pb1;
    const float4 f4z = make_float4(0.f, 0.f, 0.f, 0.f);

    auto loadA = [&](int k0) {
        if (ATR) {
            const float* p = &A[(size_t)(row0 + trr) * lda + k0 + trk];
            pa0 = *reinterpret_cast<const float4*>(p);                      // k%8 chunk: always valid
            pa1 = (k0 + 16 <= K) ? *reinterpret_cast<const float4*>(p + 8) : f4z;
        } else {
            int gk = k0 + dk;
            if (gk < K) {
                const float* p = &A[(size_t)gk * lda + row0 + dc];
                pa0 = *reinterpret_cast<const float4*>(p);
                pa1 = *reinterpret_cast<const float4*>(p + 4);
            } else { pa0 = f4z; pa1 = f4z; }
        }
    };
    auto loadB = [&](int k0) {
        if (BTR) {
            const float* p = &B[(size_t)(col0 + trr) * ldb + k0 + trk];
            pb0 = *reinterpret_cast<const float4*>(p);
            pb1 = (k0 + 16 <= K) ? *reinterpret_cast<const float4*>(p + 8) : f4z;
        } else {
            int gk = k0 + dk;
            int gc = col0 + dc;
            if (gk < K) {
                const float* p = &B[(size_t)gk * ldb + gc];
                if (!NG || gc + 7 < N) {
                    pb0 = *reinterpret_cast<const float4*>(p);
                    pb1 = *reinterpret_cast<const float4*>(p + 4);
                } else {
                    pb0.x = (gc+0 < N) ? p[0] : 0.f;
                    pb0.y = (gc+1 < N) ? p[1] : 0.f;
                    pb0.z = (gc+2 < N) ? p[2] : 0.f;
                    pb0.w = (gc+3 < N) ? p[3] : 0.f;
                    pb1.x = (gc+4 < N) ? p[4] : 0.f;
                    pb1.y = (gc+5 < N) ? p[5] : 0.f;
                    pb1.z = (gc+6 < N) ? p[6] : 0.f;
                    pb1.w = (gc+7 < N) ? p[7] : 0.f;
                }
            } else { pb0 = f4z; pb1 = f4z; }
        }
    };
    auto storeA = [&](int buf) {
        if (ATR) {
            As[buf][trk + 0][trr] = pa0.x; As[buf][trk + 1][trr] = pa0.y;
            As[buf][trk + 2][trr] = pa0.z; As[buf][trk + 3][trr] = pa0.w;
            As[buf][trk + 8][trr] = pa1.x; As[buf][trk + 9][trr] = pa1.y;
            As[buf][trk +10][trr] = pa1.z; As[buf][trk +11][trr] = pa1.w;
        } else {
            *reinterpret_cast<float4*>(&As[buf][dk][dc    ]) = pa0;
            *reinterpret_cast<float4*>(&As[buf][dk][dc + 4]) = pa1;
        }
    };
    auto storeB = [&](int buf) {
        if (BTR) {
            Bs[buf][trk + 0][trr] = pb0.x; Bs[buf][trk + 1][trr] = pb0.y;
            Bs[buf][trk + 2][trr] = pb0.z; Bs[buf][trk + 3][trr] = pb0.w;
            Bs[buf][trk + 8][trr] = pb1.x; Bs[buf][trk + 9][trr] = pb1.y;
            Bs[buf][trk +10][trr] = pb1.z; Bs[buf][trk +11][trr] = pb1.w;
        } else {
            *reinterpret_cast<float4*>(&Bs[buf][dk][dc    ]) = pb0;
            *reinterpret_cast<float4*>(&Bs[buf][dk][dc + 4]) = pb1;
        }
    };

    int buf = 0;
    loadA(0); loadB(0);
    storeA(0); storeB(0);
    __syncthreads();

    for (int k0 = 0; k0 < K; k0 += 16) {
        const bool has_next = (k0 + 16 < K);
        if (has_next) { loadA(k0 + 16); loadB(k0 + 16); }   // LDG overlaps compute

        #pragma unroll
        for (int kk = 0; kk < 16; kk++) {
            float4 a0 = *reinterpret_cast<const float4*>(&As[buf][kk][ty * 4]);
            float4 a1 = *reinterpret_cast<const float4*>(&As[buf][kk][64 + ty * 4]);
            float4 b0 = *reinterpret_cast<const float4*>(&Bs[buf][kk][tx * 4]);
            float4 b1 = *reinterpret_cast<const float4*>(&Bs[buf][kk][64 + tx * 4]);
            float av[8] = {a0.x, a0.y, a0.z, a0.w, a1.x, a1.y, a1.z, a1.w};
            float bv[8] = {b0.x, b0.y, b0.z, b0.w, b1.x, b1.y, b1.z, b1.w};
            #pragma unroll
            for (int i = 0; i < 8; i++)
                #pragma unroll
                for (int j = 0; j < 8; j++)
                    acc[i][j] = fmaf(av[i], bv[j], acc[i][j]);
        }

        if (has_next) {
            storeA(buf ^ 1); storeB(buf ^ 1);   // other buffer: no hazard w/ compute
            __syncthreads();                    // single barrier per iteration
            buf ^= 1;
        }
    }

    #pragma unroll
    for (int ri = 0; ri < 2; ri++) {
        #pragma unroll
        for (int i = 0; i < 4; i++) {
            int r = row0 + ri * 64 + ty * 4 + i;
            float scale = 1.f;
            if (EPI == 2) scale = P1[b * LL + r] * P2[b * LL + r];
            #pragma unroll
            for (int ci = 0; ci < 2; ci++) {
                #pragma unroll
                for (int j = 0; j < 4; j++) {
                    int c = col0 + ci * 64 + tx * 4 + j;
                    if (NG && c >= N) continue;
                    float v = acc[ri * 4 + i][ci * 4 + j];
                    if (EPI == 1) v = fmaxf(v + P1[c], 0.f);
                    if (EPI == 2) v *= scale;
                    C[(size_t)r * ldc + c] = v;
                }
            }
        }
    }
}

// ---------------------------------------------------------------------------
// Alpha softmax (over l, per column m): UN-normalized exp into g_ea, 1/sum
// into g_ia.  logit[l,m] = e[l,m] * mask1[b,l]
// ---------------------------------------------------------------------------
__global__ __launch_bounds__(256)
void k_softmax_cols(const float* __restrict__ mask1) {
    int b = blockIdx.y;
    int m = blockIdx.x * 256 + threadIdx.x;
    const float* pe = g_e  + (size_t)b*LL*LL + m;
    float*       po = g_ea + (size_t)b*LL*LL + m;
    __shared__ float smk[LL];
    for (int l = threadIdx.x; l < LL; l += 256) smk[l] = mask1[b*LL + l];
    __syncthreads();
    float mx = -3.4e38f;
    for (int l = 0; l < LL; l++) {
        float v = pe[(size_t)l*LL] * smk[l];
        mx = fmaxf(mx, v);
    }
    float s = 0.f;
    for (int l = 0; l < LL; l++) {
        float t = __expf(pe[(size_t)l*LL] * smk[l] - mx);
        po[(size_t)l*LL] = t;
        s += t;
    }
    g_ia[b*LL + m] = 1.f / s;
}

// ---------------------------------------------------------------------------
// Beta softmax (over m, per row l): IN-PLACE on g_e, 1/sum into g_ib.
// ---------------------------------------------------------------------------
__global__ __launch_bounds__(256)
void k_softmax_rows(const float* __restrict__ mask2) {
    int row = blockIdx.x;        // b*LL + l
    int b = row >> 10;
    float* p = g_e + (size_t)row*LL;
    const float* mk = mask2 + b*LL;
    int tid = threadIdx.x;
    __shared__ float red[256];
    float v[4];
    float mx = -3.4e38f;
    #pragma unroll
    for (int i = 0; i < 4; i++) {
        int m = tid + i*256;
        v[i] = p[m] * mk[m];
        mx = fmaxf(mx, v[i]);
    }
    red[tid] = mx; __syncthreads();
    for (int s = 128; s > 0; s >>= 1) {
        if (tid < s) red[tid] = fmaxf(red[tid], red[tid + s]);
        __syncthreads();
    }
    mx = red[0]; __syncthreads();
    float sum = 0.f;
    #pragma unroll
    for (int i = 0; i < 4; i++) { v[i] = __expf(v[i] - mx); sum += v[i]; }
    red[tid] = sum; __syncthreads();
    for (int s = 128; s > 0; s >>= 1) {
        if (tid < s) red[tid] += red[tid + s];
        __syncthreads();
    }
    float total = red[0];
    #pragma unroll
    for (int i = 0; i < 4; i++) p[tid + i*256] = v[i];
    if (tid == 0) g_ib[row] = 1.f / total;
}

// ---------------------------------------------------------------------------
extern "C" void kernel_launch(void* const* d_in, const int* in_sizes, int n_in,
                              void* d_out, int out_size) {
    const float* s1    = (const float*)d_in[0];
    const float* s2    = (const float*)d_in[1];
    const float* mask1 = (const float*)d_in[2];
    const float* mask2 = (const float*)d_in[3];
    const float* W1    = (const float*)d_in[4];
    const float* b1    = (const float*)d_in[5];
    const float* W2    = (const float*)d_in[6];
    const float* b2    = (const float*)d_in[7];
    float* out       = (float*)d_out;
    float* out_alpha = out;
    float* out_beta  = out + (size_t)NB*LL*NI;

    float *p_t, *p_h1, *p_h2, *p_e, *p_ea, *p_ia, *p_ib;
    cudaGetSymbolAddress((void**)&p_t,  g_t);
    cudaGetSymbolAddress((void**)&p_h1, g_h1);
    cudaGetSymbolAddress((void**)&p_h2, g_h2);
    cudaGetSymbolAddress((void**)&p_e,  g_e);
    cudaGetSymbolAddress((void**)&p_ea, g_ea);
    cudaGetSymbolAddress((void**)&p_ia, g_ia);
    cudaGetSymbolAddress((void**)&p_ib, g_ib);

    dim3 blk(256);

    // ---- MLP: h = relu(relu(x@W1+b1)@W2+b2) for both streams -------------
    // M=32768 (mult of 128), N=200 (guarded), K=600/200
    {
        dim3 g1((NH + 127) / 128, NR / 128, 1);   // (2, 256)
        gemm128<1,true,false,true><<<g1, blk>>>(s1,  W1, b1, nullptr, p_t,
                                                NH, NI, NI, NH, NH, 0, 0, 0);
        gemm128<1,true,false,true><<<g1, blk>>>(p_t, W2, b2, nullptr, p_h1,
                                                NH, NH, NH, NH, NH, 0, 0, 0);
        gemm128<1,true,false,true><<<g1, blk>>>(s2,  W1, b1, nullptr, p_t,
                                                NH, NI, NI, NH, NH, 0, 0, 0);
        gemm128<1,true,false,true><<<g1, blk>>>(p_t, W2, b2, nullptr, p_h2,
                                                NH, NH, NH, NH, NH, 0, 0, 0);
    }

    // ---- e[b,l,m] = h1 @ h2^T : NT, M=N=1024, K=200 -----------------------
    {
        dim3 ge(LL / 128, LL / 128, NB);          // (8, 8, 32)
        gemm128<0,true,true,false><<<ge, blk>>>(p_h1, p_h2, nullptr, nullptr, p_e,
                                                LL, NH, NH, NH, LL,
                                                (size_t)LL*NH, (size_t)LL*NH, (size_t)LL*LL);
    }

    // ---- softmaxes (alpha first: beta overwrites g_e in place) ------------
    {
        dim3 gs(LL / 256, NB);
        k_softmax_cols<<<gs, blk>>>(mask1);
    }
    k_softmax_rows<<<NR, blk>>>(mask2);

    // ---- alphas (TN) and betas (NN): M=1024, N=600, K=1024 ----------------
    {
        dim3 ga((NI + 127) / 128, LL / 128, NB);  // (5, 8, 32)
        // alphas[b,m,d] = (inv_a*mask2)[b,m] * sum_l ea[b,l,m] * s1[b,l,d]
        gemm128<2,false,false,true><<<ga, blk>>>(p_ea, s1, p_ia, mask2, out_alpha,
                                                 NI, LL, LL, NI, NI,
                                                 (size_t)LL*LL, (size_t)LL*NI, (size_t)LL*NI);
        // betas[b,l,d] = (inv_b*mask1)[b,l] * sum_m e[b,l,m] * s2[b,m,d]
        gemm128<2,true,false,true><<<ga, blk>>>(p_e, s2, p_ib, mask1, out_beta,
                                                NI, LL, LL, NI, NI,
                                                (size_t)LL*LL, (size_t)LL*NI, (size_t)LL*NI);
    }
}

// round 13
// speedup vs baseline: 1.0408x; 1.0057x over previous
#include <cuda_runtime.h>
#include <math.h>

#define NB 32
#define LL 1024
#define NI 600
#define NH 200
#define NR (NB*LL)

// ---------------- scratch (device globals; no runtime allocation) ----------
__device__ float g_t [NR*NH];                 // MLP layer1 temp
__device__ float g_h1[NR*NH];                 // mlp(s1)
__device__ float g_h2[NR*NH];                 // mlp(s2)
__device__ float g_e [(size_t)NB*LL*LL];      // e, then in-place exp for beta
__device__ float g_ea[(size_t)NB*LL*LL];      // un-normalized exp for alpha
__device__ float g_ia[NR];                    // 1/sum per (b,m) for alpha
__device__ float g_ib[NR];                    // 1/sum per (b,l) for beta

// ---------------------------------------------------------------------------
// Unified 128x128x16 SGEMM, 256 threads, 8x8 micro-tile, double-buffered smem
// (ONE __syncthreads per K-iter), register prefetch, scalar FFMA.
//   EPI: 0 = plain store, 1 = relu(acc + P1[c]), 2 = acc * P1[b*LL+r]*P2[b*LL+r]
//   ATR: A global is [M][K] (k-contiguous, transpose on smem store)
//        else A is [K][M] (m-contiguous, direct smem store)
//   BTR: B global is [N][K] (transpose on store) else [K][N] direct
//   NG : B/N needs bounds guards (N not multiple of 128)
// Requirements: M % 128 == 0, K % 8 == 0 (K%16 handled via zero-fill tail).
// ---------------------------------------------------------------------------
template<int EPI, bool ATR, bool BTR, bool NG>
__global__ __launch_bounds__(256, 2)
void gemm128(const float* __restrict__ Ag, const float* __restrict__ Bg,
             const float* __restrict__ P1, const float* __restrict__ P2,
             float* __restrict__ Cg,
             int N, int K, int lda, int ldb, int ldc,
             size_t sA, size_t sB, size_t sC)
{
    const int b = blockIdx.z;
    const float* A = Ag + (size_t)b * sA;
    const float* B = Bg + (size_t)b * sB;
    float*       C = Cg + (size_t)b * sC;

    __shared__ __align__(16) float As[2][16][132];
    __shared__ __align__(16) float Bs[2][16][132];

    const int tid  = threadIdx.x;
    const int tx   = tid & 15;           // 0..15 col group
    const int ty   = tid >> 4;           // 0..15 row group
    const int row0 = blockIdx.y * 128;
    const int col0 = blockIdx.x * 128;

    // transpose-load mapping ([R][K] sources): 2 threads/row, chunks {trk, trk+8}
    const int trr = tid >> 1;            // 0..127
    const int trk = (tid & 1) * 4;       // 0 or 4
    // direct-load mapping ([K][C] sources): 16 threads/row, 8 floats each
    const int dk  = tid >> 4;            // 0..15
    const int dc  = (tid & 15) * 8;      // 0..120

    float acc[8][8] = {};
    float4 pa0, pa1, pb0, pb1;
    const float4 f4z = make_float4(0.f, 0.f, 0.f, 0.f);

    auto loadA = [&](int k0) {
        if (ATR) {
            const float* p = &A[(size_t)(row0 + trr) * lda + k0 + trk];
            pa0 = *reinterpret_cast<const float4*>(p);                      // k%8 chunk: always valid
            pa1 = (k0 + 16 <= K) ? *reinterpret_cast<const float4*>(p + 8) : f4z;
        } else {
            int gk = k0 + dk;
            if (gk < K) {
                const float* p = &A[(size_t)gk * lda + row0 + dc];
                pa0 = *reinterpret_cast<const float4*>(p);
                pa1 = *reinterpret_cast<const float4*>(p + 4);
            } else { pa0 = f4z; pa1 = f4z; }
        }
    };
    auto loadB = [&](int k0) {
        if (BTR) {
            const float* p = &B[(size_t)(col0 + trr) * ldb + k0 + trk];
            pb0 = *reinterpret_cast<const float4*>(p);
            pb1 = (k0 + 16 <= K) ? *reinterpret_cast<const float4*>(p + 8) : f4z;
        } else {
            int gk = k0 + dk;
            int gc = col0 + dc;
            if (gk < K) {
                const float* p = &B[(size_t)gk * ldb + gc];
                if (!NG || gc + 7 < N) {
                    pb0 = *reinterpret_cast<const float4*>(p);
                    pb1 = *reinterpret_cast<const float4*>(p + 4);
                } else {
                    pb0.x = (gc+0 < N) ? p[0] : 0.f;
                    pb0.y = (gc+1 < N) ? p[1] : 0.f;
                    pb0.z = (gc+2 < N) ? p[2] : 0.f;
                    pb0.w = (gc+3 < N) ? p[3] : 0.f;
                    pb1.x = (gc+4 < N) ? p[4] : 0.f;
                    pb1.y = (gc+5 < N) ? p[5] : 0.f;
                    pb1.z = (gc+6 < N) ? p[6] : 0.f;
                    pb1.w = (gc+7 < N) ? p[7] : 0.f;
                }
            } else { pb0 = f4z; pb1 = f4z; }
        }
    };
    auto storeA = [&](int buf) {
        if (ATR) {
            As[buf][trk + 0][trr] = pa0.x; As[buf][trk + 1][trr] = pa0.y;
            As[buf][trk + 2][trr] = pa0.z; As[buf][trk + 3][trr] = pa0.w;
            As[buf][trk + 8][trr] = pa1.x; As[buf][trk + 9][trr] = pa1.y;
            As[buf][trk +10][trr] = pa1.z; As[buf][trk +11][trr] = pa1.w;
        } else {
            *reinterpret_cast<float4*>(&As[buf][dk][dc    ]) = pa0;
            *reinterpret_cast<float4*>(&As[buf][dk][dc + 4]) = pa1;
        }
    };
    auto storeB = [&](int buf) {
        if (BTR) {
            Bs[buf][trk + 0][trr] = pb0.x; Bs[buf][trk + 1][trr] = pb0.y;
            Bs[buf][trk + 2][trr] = pb0.z; Bs[buf][trk + 3][trr] = pb0.w;
            Bs[buf][trk + 8][trr] = pb1.x; Bs[buf][trk + 9][trr] = pb1.y;
            Bs[buf][trk +10][trr] = pb1.z; Bs[buf][trk +11][trr] = pb1.w;
        } else {
            *reinterpret_cast<float4*>(&Bs[buf][dk][dc    ]) = pb0;
            *reinterpret_cast<float4*>(&Bs[buf][dk][dc + 4]) = pb1;
        }
    };

    int buf = 0;
    loadA(0); loadB(0);
    storeA(0); storeB(0);
    __syncthreads();

    for (int k0 = 0; k0 < K; k0 += 16) {
        const bool has_next = (k0 + 16 < K);
        if (has_next) { loadA(k0 + 16); loadB(k0 + 16); }   // LDG overlaps compute

        #pragma unroll
        for (int kk = 0; kk < 16; kk++) {
            float4 a0 = *reinterpret_cast<const float4*>(&As[buf][kk][ty * 4]);
            float4 a1 = *reinterpret_cast<const float4*>(&As[buf][kk][64 + ty * 4]);
            float4 b0 = *reinterpret_cast<const float4*>(&Bs[buf][kk][tx * 4]);
            float4 b1 = *reinterpret_cast<const float4*>(&Bs[buf][kk][64 + tx * 4]);
            float av[8] = {a0.x, a0.y, a0.z, a0.w, a1.x, a1.y, a1.z, a1.w};
            float bv[8] = {b0.x, b0.y, b0.z, b0.w, b1.x, b1.y, b1.z, b1.w};
            #pragma unroll
            for (int i = 0; i < 8; i++)
                #pragma unroll
                for (int j = 0; j < 8; j++)
                    acc[i][j] = fmaf(av[i], bv[j], acc[i][j]);
        }

        if (has_next) {
            storeA(buf ^ 1); storeB(buf ^ 1);   // other buffer: no hazard w/ compute
            __syncthreads();                    // single barrier per iteration
            buf ^= 1;
        }
    }

    #pragma unroll
    for (int ri = 0; ri < 2; ri++) {
        #pragma unroll
        for (int i = 0; i < 4; i++) {
            int r = row0 + ri * 64 + ty * 4 + i;
            float scale = 1.f;
            if (EPI == 2) scale = P1[b * LL + r] * P2[b * LL + r];
            #pragma unroll
            for (int ci = 0; ci < 2; ci++) {
                #pragma unroll
                for (int j = 0; j < 4; j++) {
                    int c = col0 + ci * 64 + tx * 4 + j;
                    if (NG && c >= N) continue;
                    float v = acc[ri * 4 + i][ci * 4 + j];
                    if (EPI == 1) v = fmaxf(v + P1[c], 0.f);
                    if (EPI == 2) v *= scale;
                    C[(size_t)r * ldc + c] = v;
                }
            }
        }
    }
}

// ---------------------------------------------------------------------------
// Alpha softmax (over l, per column m): UN-normalized exp into g_ea, 1/sum
// into g_ia.  logit[l,m] = e[l,m] * mask1[b,l]
// ---------------------------------------------------------------------------
__global__ __launch_bounds__(256)
void k_softmax_cols(const float* __restrict__ mask1) {
    int b = blockIdx.y;
    int m = blockIdx.x * 256 + threadIdx.x;
    const float* pe = g_e  + (size_t)b*LL*LL + m;
    float*       po = g_ea + (size_t)b*LL*LL + m;
    __shared__ float smk[LL];
    for (int l = threadIdx.x; l < LL; l += 256) smk[l] = mask1[b*LL + l];
    __syncthreads();
    float mx = -3.4e38f;
    for (int l = 0; l < LL; l++) {
        float v = pe[(size_t)l*LL] * smk[l];
        mx = fmaxf(mx, v);
    }
    float s = 0.f;
    for (int l = 0; l < LL; l++) {
        float t = __expf(pe[(size_t)l*LL] * smk[l] - mx);
        po[(size_t)l*LL] = t;
        s += t;
    }
    g_ia[b*LL + m] = 1.f / s;
}

// ---------------------------------------------------------------------------
// Beta softmax (over m, per row l): IN-PLACE on g_e, 1/sum into g_ib.
// ---------------------------------------------------------------------------
__global__ __launch_bounds__(256)
void k_softmax_rows(const float* __restrict__ mask2) {
    int row = blockIdx.x;        // b*LL + l
    int b = row >> 10;
    float* p = g_e + (size_t)row*LL;
    const float* mk = mask2 + b*LL;
    int tid = threadIdx.x;
    __shared__ float red[256];
    float v[4];
    float mx = -3.4e38f;
    #pragma unroll
    for (int i = 0; i < 4; i++) {
        int m = tid + i*256;
        v[i] = p[m] * mk[m];
        mx = fmaxf(mx, v[i]);
    }
    red[tid] = mx; __syncthreads();
    for (int s = 128; s > 0; s >>= 1) {
        if (tid < s) red[tid] = fmaxf(red[tid], red[tid + s]);
        __syncthreads();
    }
    mx = red[0]; __syncthreads();
    float sum = 0.f;
    #pragma unroll
    for (int i = 0; i < 4; i++) { v[i] = __expf(v[i] - mx); sum += v[i]; }
    red[tid] = sum; __syncthreads();
    for (int s = 128; s > 0; s >>= 1) {
        if (tid < s) red[tid] += red[tid + s];
        __syncthreads();
    }
    float total = red[0];
    #pragma unroll
    for (int i = 0; i < 4; i++) p[tid + i*256] = v[i];
    if (tid == 0) g_ib[row] = 1.f / total;
}

// ---------------------------------------------------------------------------
extern "C" void kernel_launch(void* const* d_in, const int* in_sizes, int n_in,
                              void* d_out, int out_size) {
    const float* s1    = (const float*)d_in[0];
    const float* s2    = (const float*)d_in[1];
    const float* mask1 = (const float*)d_in[2];
    const float* mask2 = (const float*)d_in[3];
    const float* W1    = (const float*)d_in[4];
    const float* b1    = (const float*)d_in[5];
    const float* W2    = (const float*)d_in[6];
    const float* b2    = (const float*)d_in[7];
    float* out       = (float*)d_out;
    float* out_alpha = out;
    float* out_beta  = out + (size_t)NB*LL*NI;

    float *p_t, *p_h1, *p_h2, *p_e, *p_ea, *p_ia, *p_ib;
    cudaGetSymbolAddress((void**)&p_t,  g_t);
    cudaGetSymbolAddress((void**)&p_h1, g_h1);
    cudaGetSymbolAddress((void**)&p_h2, g_h2);
    cudaGetSymbolAddress((void**)&p_e,  g_e);
    cudaGetSymbolAddress((void**)&p_ea, g_ea);
    cudaGetSymbolAddress((void**)&p_ia, g_ia);
    cudaGetSymbolAddress((void**)&p_ib, g_ib);

    dim3 blk(256);

    // ---- MLP: h = relu(relu(x@W1+b1)@W2+b2) for both streams -------------
    // M=32768 (mult of 128), N=200 (guarded), K=600/200
    {
        dim3 g1((NH + 127) / 128, NR / 128, 1);   // (2, 256)
        gemm128<1,true,false,true><<<g1, blk>>>(s1,  W1, b1, nullptr, p_t,
                                                NH, NI, NI, NH, NH, 0, 0, 0);
        gemm128<1,true,false,true><<<g1, blk>>>(p_t, W2, b2, nullptr, p_h1,
                                                NH, NH, NH, NH, NH, 0, 0, 0);
        gemm128<1,true,false,true><<<g1, blk>>>(s2,  W1, b1, nullptr, p_t,
                                                NH, NI, NI, NH, NH, 0, 0, 0);
        gemm128<1,true,false,true><<<g1, blk>>>(p_t, W2, b2, nullptr, p_h2,
                                                NH, NH, NH, NH, NH, 0, 0, 0);
    }

    // ---- e[b,l,m] = h1 @ h2^T : NT, M=N=1024, K=200 -----------------------
    {
        dim3 ge(LL / 128, LL / 128, NB);          // (8, 8, 32)
        gemm128<0,true,true,false><<<ge, blk>>>(p_h1, p_h2, nullptr, nullptr, p_e,
                                                LL, NH, NH, NH, LL,
                                                (size_t)LL*NH, (size_t)LL*NH, (size_t)LL*LL);
    }

    // ---- softmaxes (alpha first: beta overwrites g_e in place) ------------
    {
        dim3 gs(LL / 256, NB);
        k_softmax_cols<<<gs, blk>>>(mask1);
    }
    k_softmax_rows<<<NR, blk>>>(mask2);

    // ---- alphas (TN) and betas (NN): M=1024, N=600, K=1024 ----------------
    {
        dim3 ga((NI + 127) / 128, LL / 128, NB);  // (5, 8, 32)
        // alphas[b,m,d] = (inv_a*mask2)[b,m] * sum_l ea[b,l,m] * s1[b,l,d]
        gemm128<2,false,false,true><<<ga, blk>>>(p_ea, s1, p_ia, mask2, out_alpha,
                                                 NI, LL, LL, NI, NI,
                                                 (size_t)LL*LL, (size_t)LL*NI, (size_t)LL*NI);
        // betas[b,l,d] = (inv_b*mask1)[b,l] * sum_m e[b,l,m] * s2[b,m,d]
        gemm128<2,true,false,true><<<ga, blk>>>(p_e, s2, p_ib, mask1, out_beta,
                                                NI, LL, LL, NI, NI,
                                                (size_t)LL*LL, (size_t)LL*NI, (size_t)LL*NI);
    }
}

// round 15
// speedup vs baseline: 1.9071x; 1.8323x over previous
#include <cuda_runtime.h>
#include <cuda_bf16.h>
#include <math.h>
#include <cstdint>

#define NB 32
#define LL 1024
#define NI 600
#define NH 200
#define NR (NB*LL)
#define KH 256      // padded K for h pairs (200 -> 256)
#define DP 640      // padded d rows for transposed s (600 -> 640)

// ---------------- scratch (device globals; no runtime allocation) ----------
__device__ __align__(16) float g_t [NR*NH];
__device__ __align__(16) __nv_bfloat16 g_h1h[(size_t)NR*KH];
__device__ __align__(16) __nv_bfloat16 g_h1l[(size_t)NR*KH];
__device__ __align__(16) __nv_bfloat16 g_h2h[(size_t)NR*KH];
__device__ __align__(16) __nv_bfloat16 g_h2l[(size_t)NR*KH];
__device__ __align__(16) float g_e [(size_t)NB*LL*LL];
__device__ __align__(16) __nv_bfloat16 g_eah[(size_t)NB*LL*LL]; // exp_a^T [b][m][l]
__device__ __align__(16) __nv_bfloat16 g_eal[(size_t)NB*LL*LL];
__device__ __align__(16) __nv_bfloat16 g_ebh[(size_t)NB*LL*LL]; // exp_b [b][l][m]
__device__ __align__(16) __nv_bfloat16 g_ebl[(size_t)NB*LL*LL];
__device__ __align__(16) __nv_bfloat16 g_s1h[(size_t)NB*DP*LL]; // s1^T [b][d][l]
__device__ __align__(16) __nv_bfloat16 g_s1l[(size_t)NB*DP*LL];
__device__ __align__(16) __nv_bfloat16 g_s2h[(size_t)NB*DP*LL];
__device__ __align__(16) __nv_bfloat16 g_s2l[(size_t)NB*DP*LL];
__device__ float g_ia[NR];
__device__ float g_ib[NR];

// ======================= low-level helpers (sm_80-safe PTX only) ===========
static __device__ __forceinline__ uint32_t smem_u32(const void* p) {
    uint32_t a;
    asm("{ .reg .u64 t; cvta.to.shared.u64 t, %1; cvt.u32.u64 %0, t; }" : "=r"(a) : "l"(p));
    return a;
}
static __device__ __forceinline__ uint32_t lds32(uint32_t a) {
    uint32_t v;
    asm volatile("ld.shared.b32 %0, [%1];" : "=r"(v) : "r"(a));
    return v;
}
static __device__ __forceinline__ void cpasync16(uint32_t s, const void* g) {
    asm volatile("cp.async.cg.shared.global [%0], [%1], 16;" :: "r"(s), "l"(g) : "memory");
}
#define CP_COMMIT() asm volatile("cp.async.commit_group;" ::: "memory")
template<int N> static __device__ __forceinline__ void cp_wait() {
    asm volatile("cp.async.wait_group %0;" :: "n"(N) : "memory");
}
static __device__ __forceinline__ void mma_bf16(float* d, const uint32_t* a, const uint32_t* b) {
    asm volatile(
        "mma.sync.aligned.m16n8k16.row.col.f32.bf16.bf16.f32 "
        "{%0,%1,%2,%3}, {%4,%5,%6,%7}, {%8,%9}, {%0,%1,%2,%3};"
        : "+f"(d[0]), "+f"(d[1]), "+f"(d[2]), "+f"(d[3])
        : "r"(a[0]), "r"(a[1]), "r"(a[2]), "r"(a[3]), "r"(b[0]), "r"(b[1]));
}

// ---------------------------------------------------------------------------
// Tensor GEMM via mma.sync (HMMA): C[r][n] = sum_k A[r][k]*B[n][k],
// bf16 hi/lo split (3 MMA passes), fp32 accum.
// CTA tile 128x128, K-chunk 32, cp.async double-buffered smem.
// smem rows padded to 80B -> all fragment LDS are bank-conflict-free.
//   EPI 0: C = acc          EPI 2: C = acc * P1[b*LL+r] * P2[b*LL+r]
// Requires: M,K multiples of tile; B rows (N dim) padded; Nv guards stores.
// ---------------------------------------------------------------------------
#define RSB  80                 // smem row stride (bytes) for 32 bf16 + pad
#define ARRB (128*RSB)          // one array (10240 B)
#define BUFB (4*ARRB)           // Ah,Al,Bh,Bl per buffer (40960 B)

template<int EPI>
__global__ __launch_bounds__(256, 2)
void gemm_mma(const __nv_bfloat16* __restrict__ Ah, const __nv_bfloat16* __restrict__ Al,
              const __nv_bfloat16* __restrict__ Bh, const __nv_bfloat16* __restrict__ Bl,
              const float* __restrict__ P1, const float* __restrict__ P2,
              float* __restrict__ Cg,
              int K, int ldka, int ldkb, int ldc, int Nv,
              size_t sA, size_t sB, size_t sC)
{
    extern __shared__ __align__(16) char smem[];
    const int b    = blockIdx.z;
    const int row0 = blockIdx.y * 128;
    const int col0 = blockIdx.x * 128;
    const __nv_bfloat16* pAh = Ah + (size_t)b * sA;
    const __nv_bfloat16* pAl = Al + (size_t)b * sA;
    const __nv_bfloat16* pBh = Bh + (size_t)b * sB;
    const __nv_bfloat16* pBl = Bl + (size_t)b * sB;

    const uint32_t sb = smem_u32(smem);
    const int tid  = threadIdx.x;
    const int wid  = tid >> 5;
    const int lane = tid & 31;
    const int wm   = (wid & 1) * 64;      // warp row offset in tile
    const int wn   = (wid >> 1) * 32;     // warp col offset in tile
    const int g    = lane >> 2;           // group 0..7
    const int tig  = lane & 3;            // thread-in-group

    // staging: 512 16B-chunks per array; thread t handles chunks t and t+256
    const int r0s = tid >> 2,        c0s = tid & 3;
    const int r1s = (tid + 256) >> 2, c1s = (tid + 256) & 3;

    auto stage = [&](int kc, int buf) {
        const uint32_t base = sb + buf * BUFB;
        const int k0 = kc * 32;
        // A rows: row0 + r ; B rows: col0 + r
        cpasync16(base            + r0s*RSB + c0s*16, pAh + (size_t)(row0+r0s)*ldka + k0 + c0s*8);
        cpasync16(base            + r1s*RSB + c1s*16, pAh + (size_t)(row0+r1s)*ldka + k0 + c1s*8);
        cpasync16(base +   ARRB   + r0s*RSB + c0s*16, pAl + (size_t)(row0+r0s)*ldka + k0 + c0s*8);
        cpasync16(base +   ARRB   + r1s*RSB + c1s*16, pAl + (size_t)(row0+r1s)*ldka + k0 + c1s*8);
        cpasync16(base + 2*ARRB   + r0s*RSB + c0s*16, pBh + (size_t)(col0+r0s)*ldkb + k0 + c0s*8);
        cpasync16(base + 2*ARRB   + r1s*RSB + c1s*16, pBh + (size_t)(col0+r1s)*ldkb + k0 + c1s*8);
        cpasync16(base + 3*ARRB   + r0s*RSB + c0s*16, pBl + (size_t)(row0 ? (col0+r0s) : (col0+r0s))*ldkb + k0 + c0s*8);
        cpasync16(base + 3*ARRB   + r1s*RSB + c1s*16, pBl + (size_t)(col0+r1s)*ldkb + k0 + c1s*8);
    };

    float acc[4][4][4] = {};

    stage(0, 0); CP_COMMIT();
    const int nc = K / 32;
    for (int c = 0; c < nc; c++) {
        const int buf = c & 1;
        if (c + 1 < nc) { stage(c + 1, buf ^ 1); CP_COMMIT(); cp_wait<1>(); }
        else            { cp_wait<0>(); }
        __syncthreads();

        const uint32_t aB = sb + buf * BUFB;
        #pragma unroll
        for (int kk = 0; kk < 2; kk++) {                // two k16 steps per chunk
            const uint32_t kb = kk * 32 + tig * 4;      // byte offset of k-pair
            #pragma unroll
            for (int sp = 0; sp < 3; sp++) {            // hi*hi, hi*lo, lo*hi
                const uint32_t Abase = aB + (sp == 2 ? ARRB : 0u);
                const uint32_t Bbase = aB + 2*ARRB + (sp == 1 ? ARRB : 0u);
                uint32_t af[4][4], bf[4][2];
                #pragma unroll
                for (int mt = 0; mt < 4; mt++) {
                    uint32_t ra = Abase + (uint32_t)(wm + mt*16 + g) * RSB + kb;
                    af[mt][0] = lds32(ra);
                    af[mt][1] = lds32(ra + 8*RSB);
                    af[mt][2] = lds32(ra + 16);
                    af[mt][3] = lds32(ra + 8*RSB + 16);
                }
                #pragma unroll
                for (int nt = 0; nt < 4; nt++) {
                    uint32_t rb = Bbase + (uint32_t)(wn + nt*8 + g) * RSB + kb;
                    bf[nt][0] = lds32(rb);
                    bf[nt][1] = lds32(rb + 16);
                }
                #pragma unroll
                for (int mt = 0; mt < 4; mt++)
                    #pragma unroll
                    for (int nt = 0; nt < 4; nt++)
                        mma_bf16(acc[mt][nt], af[mt], bf[nt]);
            }
        }
        __syncthreads();
    }

    // ---- epilogue: c0,c1 -> row g ; c2,c3 -> row g+8 ; cols 2tig,2tig+1 ----
    #pragma unroll
    for (int mt = 0; mt < 4; mt++) {
        const int r_lo = row0 + wm + mt*16 + g;
        const int r_hi = r_lo + 8;
        float s_lo = 1.f, s_hi = 1.f;
        if (EPI == 2) {
            s_lo = P1[b*LL + r_lo] * P2[b*LL + r_lo];
            s_hi = P1[b*LL + r_hi] * P2[b*LL + r_hi];
        }
        float* C0 = Cg + (size_t)b * sC + (size_t)r_lo * ldc;
        float* C1 = Cg + (size_t)b * sC + (size_t)r_hi * ldc;
        #pragma unroll
        for (int nt = 0; nt < 4; nt++) {
            const int cc = col0 + wn + nt*8 + tig*2;
            if (cc < Nv) {
                float2 v0 = make_float2(acc[mt][nt][0] * s_lo, acc[mt][nt][1] * s_lo);
                float2 v1 = make_float2(acc[mt][nt][2] * s_hi, acc[mt][nt][3] * s_hi);
                *reinterpret_cast<float2*>(C0 + cc) = v0;
                *reinterpret_cast<float2*>(C1 + cc) = v1;
            }
        }
    }
}

// ---------------------------------------------------------------------------
// FFMA 128x128x16 SGEMM for MLP. A [M][K] fp32 (transpose-stored), B=W [K][N].
//   EPI 1: fp32 relu(acc+bias) -> C      EPI 3: bf16 hi/lo relu, pad to KH
// ---------------------------------------------------------------------------
template<int EPI>
__global__ __launch_bounds__(256, 2)
void gemm128(const float* __restrict__ A, const float* __restrict__ B,
             const float* __restrict__ bias, float* __restrict__ C,
             __nv_bfloat16* __restrict__ Oh, __nv_bfloat16* __restrict__ Ol,
             int N, int K, int lda, int ldb, int ldc)
{
    __shared__ __align__(16) float As[2][16][132];
    __shared__ __align__(16) float Bs[2][16][132];

    const int tid  = threadIdx.x;
    const int tx   = tid & 15, ty = tid >> 4;
    const int row0 = blockIdx.y * 128, col0 = blockIdx.x * 128;
    const int trr = tid >> 1, trk = (tid & 1) * 4;
    const int dk  = tid >> 4, dc = (tid & 15) * 8;

    float acc[8][8] = {};
    float4 pa0, pa1, pb0, pb1;
    const float4 f4z = make_float4(0.f, 0.f, 0.f, 0.f);

    auto loadA = [&](int k0) {
        const float* p = &A[(size_t)(row0 + trr) * lda + k0 + trk];
        pa0 = *reinterpret_cast<const float4*>(p);
        pa1 = (k0 + 16 <= K) ? *reinterpret_cast<const float4*>(p + 8) : f4z;
    };
    auto loadB = [&](int k0) {
        int gk = k0 + dk, gc = col0 + dc;
        if (gk < K) {
            const float* p = &B[(size_t)gk * ldb + gc];
            if (gc + 7 < N) {
                pb0 = *reinterpret_cast<const float4*>(p);
                pb1 = *reinterpret_cast<const float4*>(p + 4);
            } else {
                pb0.x = (gc+0<N)?p[0]:0.f; pb0.y = (gc+1<N)?p[1]:0.f;
                pb0.z = (gc+2<N)?p[2]:0.f; pb0.w = (gc+3<N)?p[3]:0.f;
                pb1.x = (gc+4<N)?p[4]:0.f; pb1.y = (gc+5<N)?p[5]:0.f;
                pb1.z = (gc+6<N)?p[6]:0.f; pb1.w = (gc+7<N)?p[7]:0.f;
            }
        } else { pb0 = f4z; pb1 = f4z; }
    };
    auto storeA = [&](int buf) {
        As[buf][trk + 0][trr] = pa0.x; As[buf][trk + 1][trr] = pa0.y;
        As[buf][trk + 2][trr] = pa0.z; As[buf][trk + 3][trr] = pa0.w;
        As[buf][trk + 8][trr] = pa1.x; As[buf][trk + 9][trr] = pa1.y;
        As[buf][trk +10][trr] = pa1.z; As[buf][trk +11][trr] = pa1.w;
    };
    auto storeB = [&](int buf) {
        *reinterpret_cast<float4*>(&Bs[buf][dk][dc    ]) = pb0;
        *reinterpret_cast<float4*>(&Bs[buf][dk][dc + 4]) = pb1;
    };

    int buf = 0;
    loadA(0); loadB(0);
    storeA(0); storeB(0);
    __syncthreads();

    for (int k0 = 0; k0 < K; k0 += 16) {
        const bool has_next = (k0 + 16 < K);
        if (has_next) { loadA(k0 + 16); loadB(k0 + 16); }
        #pragma unroll
        for (int kk = 0; kk < 16; kk++) {
            float4 a0 = *reinterpret_cast<const float4*>(&As[buf][kk][ty * 4]);
            float4 a1 = *reinterpret_cast<const float4*>(&As[buf][kk][64 + ty * 4]);
            float4 b0 = *reinterpret_cast<const float4*>(&Bs[buf][kk][tx * 4]);
            float4 b1 = *reinterpret_cast<const float4*>(&Bs[buf][kk][64 + tx * 4]);
            float av[8] = {a0.x, a0.y, a0.z, a0.w, a1.x, a1.y, a1.z, a1.w};
            float bv[8] = {b0.x, b0.y, b0.z, b0.w, b1.x, b1.y, b1.z, b1.w};
            #pragma unroll
            for (int i = 0; i < 8; i++)
                #pragma unroll
                for (int j = 0; j < 8; j++)
                    acc[i][j] = fmaf(av[i], bv[j], acc[i][j]);
        }
        if (has_next) {
            storeA(buf ^ 1); storeB(buf ^ 1);
            __syncthreads();
            buf ^= 1;
        }
    }

    #pragma unroll
    for (int ri = 0; ri < 2; ri++)
        #pragma unroll
        for (int i = 0; i < 4; i++) {
            int r = row0 + ri * 64 + ty * 4 + i;
            #pragma unroll
            for (int ci = 0; ci < 2; ci++)
                #pragma unroll
                for (int j = 0; j < 4; j++) {
                    int c = col0 + ci * 64 + tx * 4 + j;
                    float a = acc[ri * 4 + i][ci * 4 + j];
                    if (EPI == 1) {
                        if (c < N) C[(size_t)r * ldc + c] = fmaxf(a + bias[c], 0.f);
                    } else {
                        float v = (c < N) ? fmaxf(a + bias[c], 0.f) : 0.f;
                        __nv_bfloat16 hi = __float2bfloat16(v);
                        Oh[(size_t)r * KH + c] = hi;
                        Ol[(size_t)r * KH + c] = __float2bfloat16(v - __bfloat162float(hi));
                    }
                }
        }
}

// ---------------------------------------------------------------------------
// s [b][l][d] fp32 -> [b][DP][LL] bf16 hi/lo (transposed, zero-padded d)
// ---------------------------------------------------------------------------
__global__ __launch_bounds__(256)
void k_split_transpose(const float* __restrict__ S,
                       __nv_bfloat16* __restrict__ Th,
                       __nv_bfloat16* __restrict__ Tl)
{
    __shared__ float tile[32][33];
    int b  = blockIdx.z;
    int l0 = blockIdx.x * 32;
    int d0 = blockIdx.y * 32;
    int tx = threadIdx.x & 31, ty = threadIdx.x >> 5;   // ty 0..7
    #pragma unroll
    for (int i = 0; i < 4; i++) {
        int l = l0 + ty + i * 8, d = d0 + tx;
        tile[ty + i * 8][tx] = (d < NI) ? S[((size_t)b * LL + l) * NI + d] : 0.f;
    }
    __syncthreads();
    #pragma unroll
    for (int i = 0; i < 4; i++) {
        int d = d0 + ty + i * 8;
        float v = tile[tx][ty + i * 8];
        __nv_bfloat16 hi = __float2bfloat16(v);
        size_t o = ((size_t)b * DP + d) * LL + l0 + tx;
        Th[o] = hi;
        Tl[o] = __float2bfloat16(v - __bfloat162float(hi));
    }
}

// ---------------------------------------------------------------------------
// Alpha softmax over l per column m: unnormalized exp TRANSPOSED -> g_eah/l
// ([b][m][l] bf16 pairs), 1/sum -> g_ia. logit = e[l,m]*mask1[b,l].
// block 256 = 32 m-cols x 8 l-groups; grid (LL/32, NB).
// ---------------------------------------------------------------------------
__global__ __launch_bounds__(256)
void k_softmax_cols(const float* __restrict__ mask1) {
    int b  = blockIdx.y;
    int m0 = blockIdx.x * 32;
    int tx = threadIdx.x & 31, ty = threadIdx.x >> 5;   // ty 0..7
    const float* pe = g_e + (size_t)b * LL * LL;
    __shared__ float smk[LL];
    __shared__ float red[8][33];
    __shared__ float tile[32][33];
    for (int l = threadIdx.x; l < LL; l += 256) smk[l] = mask1[b * LL + l];
    __syncthreads();

    float mx = -3.4e38f;
    for (int l = ty; l < LL; l += 8)
        mx = fmaxf(mx, pe[(size_t)l * LL + m0 + tx] * smk[l]);
    red[ty][tx] = mx;
    __syncthreads();
    mx = red[0][tx];
    #pragma unroll
    for (int j = 1; j < 8; j++) mx = fmaxf(mx, red[j][tx]);

    float sum = 0.f;
    for (int l0 = 0; l0 < LL; l0 += 32) {
        #pragma unroll
        for (int i = 0; i < 4; i++) {
            int lo = ty * 4 + i;
            int l  = l0 + lo;
            float t = __expf(pe[(size_t)l * LL + m0 + tx] * smk[l] - mx);
            sum += t;                     // per column m0+tx
            tile[tx][lo] = t;             // [m_local][l_local]
        }
        __syncthreads();
        #pragma unroll
        for (int i = 0; i < 4; i++) {
            int m = ty * 4 + i;
            float t = tile[m][tx];
            __nv_bfloat16 hi = __float2bfloat16(t);
            size_t o = ((size_t)b * LL + m0 + m) * LL + l0 + tx;
            g_eah[o] = hi;
            g_eal[o] = __float2bfloat16(t - __bfloat162float(hi));
        }
        __syncthreads();
    }
    red[ty][tx] = sum;
    __syncthreads();
    if (ty == 0) {
        float s = 0.f;
        #pragma unroll
        for (int j = 0; j < 8; j++) s += red[j][tx];
        g_ia[b * LL + m0 + tx] = 1.f / s;
    }
}

// ---------------------------------------------------------------------------
// Beta softmax over m per row l: unnormalized exp -> g_ebh/l [b][l][m] pairs,
// 1/sum -> g_ib. logit = e[l,m]*mask2[b,m].
// ---------------------------------------------------------------------------
__global__ __launch_bounds__(256)
void k_softmax_rows(const float* __restrict__ mask2) {
    int row = blockIdx.x;        // b*LL + l
    int b = row >> 10;
    const float* p = g_e + (size_t)row * LL;
    const float* mk = mask2 + b * LL;
    int tid = threadIdx.x;
    __shared__ float red[256];
    float v[4];
    float mx = -3.4e38f;
    #pragma unroll
    for (int i = 0; i < 4; i++) {
        int m = tid + i * 256;
        v[i] = p[m] * mk[m];
        mx = fmaxf(mx, v[i]);
    }
    red[tid] = mx; __syncthreads();
    for (int s = 128; s > 0; s >>= 1) {
        if (tid < s) red[tid] = fmaxf(red[tid], red[tid + s]);
        __syncthreads();
    }
    mx = red[0]; __syncthreads();
    float sum = 0.f;
    #pragma unroll
    for (int i = 0; i < 4; i++) { v[i] = __expf(v[i] - mx); sum += v[i]; }
    red[tid] = sum; __syncthreads();
    for (int s = 128; s > 0; s >>= 1) {
        if (tid < s) red[tid] += red[tid + s];
        __syncthreads();
    }
    float total = red[0];
    #pragma unroll
    for (int i = 0; i < 4; i++) {
        int m = tid + i * 256;
        __nv_bfloat16 hi = __float2bfloat16(v[i]);
        g_ebh[(size_t)row * LL + m] = hi;
        g_ebl[(size_t)row * LL + m] = __float2bfloat16(v[i] - __bfloat162float(hi));
    }
    if (tid == 0) g_ib[row] = 1.f / total;
}

// ---------------------------------------------------------------------------
extern "C" void kernel_launch(void* const* d_in, const int* in_sizes, int n_in,
                              void* d_out, int out_size) {
    const float* s1    = (const float*)d_in[0];
    const float* s2    = (const float*)d_in[1];
    const float* mask1 = (const float*)d_in[2];
    const float* mask2 = (const float*)d_in[3];
    const float* W1    = (const float*)d_in[4];
    const float* b1    = (const float*)d_in[5];
    const float* W2    = (const float*)d_in[6];
    const float* b2    = (const float*)d_in[7];
    float* out       = (float*)d_out;
    float* out_alpha = out;
    float* out_beta  = out + (size_t)NB*LL*NI;

    float *p_t, *p_e, *p_ia, *p_ib;
    __nv_bfloat16 *p_h1h, *p_h1l, *p_h2h, *p_h2l;
    __nv_bfloat16 *p_eah, *p_eal, *p_ebh, *p_ebl;
    __nv_bfloat16 *p_s1h, *p_s1l, *p_s2h, *p_s2l;
    cudaGetSymbolAddress((void**)&p_t,   g_t);
    cudaGetSymbolAddress((void**)&p_e,   g_e);
    cudaGetSymbolAddress((void**)&p_ia,  g_ia);
    cudaGetSymbolAddress((void**)&p_ib,  g_ib);
    cudaGetSymbolAddress((void**)&p_h1h, g_h1h);
    cudaGetSymbolAddress((void**)&p_h1l, g_h1l);
    cudaGetSymbolAddress((void**)&p_h2h, g_h2h);
    cudaGetSymbolAddress((void**)&p_h2l, g_h2l);
    cudaGetSymbolAddress((void**)&p_eah, g_eah);
    cudaGetSymbolAddress((void**)&p_eal, g_eal);
    cudaGetSymbolAddress((void**)&p_ebh, g_ebh);
    cudaGetSymbolAddress((void**)&p_ebl, g_ebl);
    cudaGetSymbolAddress((void**)&p_s1h, g_s1h);
    cudaGetSymbolAddress((void**)&p_s1l, g_s1l);
    cudaGetSymbolAddress((void**)&p_s2h, g_s2h);
    cudaGetSymbolAddress((void**)&p_s2l, g_s2l);

    const int MMA_SMEM = 2 * BUFB;   // 81920
    cudaFuncSetAttribute(gemm_mma<0>, cudaFuncAttributeMaxDynamicSharedMemorySize, MMA_SMEM);
    cudaFuncSetAttribute(gemm_mma<2>, cudaFuncAttributeMaxDynamicSharedMemorySize, MMA_SMEM);

    dim3 blk(256);

    // ---- split+transpose s1/s2 -> [b][d][l] bf16 pairs --------------------
    {
        dim3 gt(LL / 32, DP / 32, NB);
        k_split_transpose<<<gt, blk>>>(s1, p_s1h, p_s1l);
        k_split_transpose<<<gt, blk>>>(s2, p_s2h, p_s2l);
    }

    // ---- MLP (FFMA): layer1 fp32, layer2 -> bf16 pairs padded to KH -------
    {
        dim3 g1(2, NR / 128);
        gemm128<1><<<g1, blk>>>(s1,  W1, b1, p_t, nullptr, nullptr, NH, NI, NI, NH, NH);
        gemm128<3><<<g1, blk>>>(p_t, W2, b2, nullptr, p_h1h, p_h1l, NH, NH, NH, NH, 0);
        gemm128<1><<<g1, blk>>>(s2,  W1, b1, p_t, nullptr, nullptr, NH, NI, NI, NH, NH);
        gemm128<3><<<g1, blk>>>(p_t, W2, b2, nullptr, p_h2h, p_h2l, NH, NH, NH, NH, 0);
    }

    // ---- e[b,l,m] = h1 . h2 (both K-major over KH) : tensor (mma.sync) ----
    {
        dim3 ge(LL / 128, LL / 128, NB);
        gemm_mma<0><<<ge, blk, MMA_SMEM>>>(p_h1h, p_h1l, p_h2h, p_h2l,
                                           nullptr, nullptr, p_e,
                                           KH, KH, KH, LL, LL,
                                           (size_t)LL*KH, (size_t)LL*KH, (size_t)LL*LL);
    }

    // ---- softmaxes ---------------------------------------------------------
    {
        dim3 gs(LL / 32, NB);
        k_softmax_cols<<<gs, blk>>>(mask1);
    }
    k_softmax_rows<<<NR, blk>>>(mask2);

    // ---- alphas / betas : tensor (mma.sync), K = LL ------------------------
    {
        dim3 ga(DP / 128, LL / 128, NB);   // (5, 8, 32)
        gemm_mma<2><<<ga, blk, MMA_SMEM>>>(p_eah, p_eal, p_s1h, p_s1l,
                                           p_ia, mask2, out_alpha,
                                           LL, LL, LL, NI, NI,
                                           (size_t)LL*LL, (size_t)DP*LL, (size_t)LL*NI);
        gemm_mma<2><<<ga, blk, MMA_SMEM>>>(p_ebh, p_ebl, p_s2h, p_s2l,
                                           p_ib, mask1, out_beta,
                                           LL, LL, LL, NI, NI,
                                           (size_t)LL*LL, (size_t)DP*LL, (size_t)LL*NI);
    }
}

// round 16
// speedup vs baseline: 2.2841x; 1.1977x over previous
#include <cuda_runtime.h>
#include <cuda_bf16.h>
#include <math.h>
#include <cstdint>

#define NB 32
#define LL 1024
#define NI 600
#define NH 200
#define NR (NB*LL)
#define KH 256      // padded K for h/t pairs (200 -> 256)
#define DP 640      // padded d (600 -> 640)

// ---------------- scratch (device globals; no runtime allocation) ----------
__device__ __align__(16) __nv_bfloat16 g_tph[(size_t)NR*KH];    // MLP L1 out pairs
__device__ __align__(16) __nv_bfloat16 g_tpl[(size_t)NR*KH];
__device__ __align__(16) __nv_bfloat16 g_h1h[(size_t)NR*KH];
__device__ __align__(16) __nv_bfloat16 g_h1l[(size_t)NR*KH];
__device__ __align__(16) __nv_bfloat16 g_h2h[(size_t)NR*KH];
__device__ __align__(16) __nv_bfloat16 g_h2l[(size_t)NR*KH];
__device__ __align__(16) float g_e [(size_t)NB*LL*LL];
__device__ __align__(16) __nv_bfloat16 g_eah[(size_t)NB*LL*LL]; // exp_a^T [b][m][l]
__device__ __align__(16) __nv_bfloat16 g_eal[(size_t)NB*LL*LL];
__device__ __align__(16) __nv_bfloat16 g_ebh[(size_t)NB*LL*LL]; // exp_b [b][l][m]
__device__ __align__(16) __nv_bfloat16 g_ebl[(size_t)NB*LL*LL];
__device__ __align__(16) __nv_bfloat16 g_s1h[(size_t)NB*DP*LL]; // s1^T [b][d][l]
__device__ __align__(16) __nv_bfloat16 g_s1l[(size_t)NB*DP*LL];
__device__ __align__(16) __nv_bfloat16 g_s2h[(size_t)NB*DP*LL];
__device__ __align__(16) __nv_bfloat16 g_s2l[(size_t)NB*DP*LL];
__device__ __align__(16) __nv_bfloat16 g_s1ph[(size_t)NR*DP];   // s1 [b][l][d] pairs
__device__ __align__(16) __nv_bfloat16 g_s1pl[(size_t)NR*DP];
__device__ __align__(16) __nv_bfloat16 g_s2ph[(size_t)NR*DP];
__device__ __align__(16) __nv_bfloat16 g_s2pl[(size_t)NR*DP];
__device__ __align__(16) __nv_bfloat16 g_w1th[256*DP];          // W1^T pairs [256][640]
__device__ __align__(16) __nv_bfloat16 g_w1tl[256*DP];
__device__ __align__(16) __nv_bfloat16 g_w2th[256*KH];          // W2^T pairs [256][256]
__device__ __align__(16) __nv_bfloat16 g_w2tl[256*KH];
__device__ float g_ia[NR];
__device__ float g_ib[NR];

// ======================= low-level helpers (sm_80-safe PTX only) ===========
static __device__ __forceinline__ uint32_t smem_u32(const void* p) {
    uint32_t a;
    asm("{ .reg .u64 t; cvta.to.shared.u64 t, %1; cvt.u32.u64 %0, t; }" : "=r"(a) : "l"(p));
    return a;
}
static __device__ __forceinline__ uint32_t lds32(uint32_t a) {
    uint32_t v;
    asm volatile("ld.shared.b32 %0, [%1];" : "=r"(v) : "r"(a));
    return v;
}
static __device__ __forceinline__ void cpasync16(uint32_t s, const void* g) {
    asm volatile("cp.async.cg.shared.global [%0], [%1], 16;" :: "r"(s), "l"(g) : "memory");
}
#define CP_COMMIT() asm volatile("cp.async.commit_group;" ::: "memory")
template<int N> static __device__ __forceinline__ void cp_wait() {
    asm volatile("cp.async.wait_group %0;" :: "n"(N) : "memory");
}
static __device__ __forceinline__ void mma_bf16(float* d, const uint32_t* a, const uint32_t* b) {
    asm volatile(
        "mma.sync.aligned.m16n8k16.row.col.f32.bf16.bf16.f32 "
        "{%0,%1,%2,%3}, {%4,%5,%6,%7}, {%8,%9}, {%0,%1,%2,%3};"
        : "+f"(d[0]), "+f"(d[1]), "+f"(d[2]), "+f"(d[3])
        : "r"(a[0]), "r"(a[1]), "r"(a[2]), "r"(a[3]), "r"(b[0]), "r"(b[1]));
}

// ---------------------------------------------------------------------------
// Tensor GEMM via mma.sync: C[r][n] = sum_k A[r][k]*B[n][k], bf16 hi/lo split
// (3 MMAs: AhBh + AhBl + AlBh), fp32 accum, fragment loads DEDUPED per split.
// CTA tile 128x128, K-chunk 32, cp.async double-buffered. Rows 80B -> no
// bank conflicts.
//   EPI 0: Cg = acc (fp32)
//   EPI 1: Oh/Ol = bf16 hi/lo of relu(acc + P1[c]) (0 for c>=Nv)
//   EPI 2: Cg = acc * P1[b*LL+r] * P2[b*LL+r]   (guard c<Nv)
// ---------------------------------------------------------------------------
#define RSB  80                 // smem row stride (bytes): 32 bf16 + pad
#define ARRB (128*RSB)          // one array (10240 B)
#define BUFB (4*ARRB)           // Ah,Al,Bh,Bl per buffer (40960 B)

template<int EPI>
__global__ __launch_bounds__(256, 2)
void gemm_mma(const __nv_bfloat16* __restrict__ Ah, const __nv_bfloat16* __restrict__ Al,
              const __nv_bfloat16* __restrict__ Bh, const __nv_bfloat16* __restrict__ Bl,
              const float* __restrict__ P1, const float* __restrict__ P2,
              float* __restrict__ Cg,
              __nv_bfloat16* __restrict__ Oh, __nv_bfloat16* __restrict__ Ol,
              int K, int ldka, int ldkb, int ldc, int Nv,
              size_t sA, size_t sB, size_t sC)
{
    extern __shared__ __align__(16) char smem[];
    const int b    = blockIdx.z;
    const int row0 = blockIdx.y * 128;
    const int col0 = blockIdx.x * 128;
    const __nv_bfloat16* pAh = Ah + (size_t)b * sA;
    const __nv_bfloat16* pAl = Al + (size_t)b * sA;
    const __nv_bfloat16* pBh = Bh + (size_t)b * sB;
    const __nv_bfloat16* pBl = Bl + (size_t)b * sB;

    const uint32_t sb = smem_u32(smem);
    const int tid  = threadIdx.x;
    const int wid  = tid >> 5;
    const int lane = tid & 31;
    const int wm   = (wid & 1) * 64;
    const int wn   = (wid >> 1) * 32;
    const int g    = lane >> 2;
    const int tig  = lane & 3;

    const int r0s = tid >> 2,         c0s = tid & 3;
    const int r1s = (tid + 256) >> 2, c1s = (tid + 256) & 3;

    auto stage = [&](int kc, int buf) {
        const uint32_t base = sb + buf * BUFB;
        const int k0 = kc * 32;
        cpasync16(base          + r0s*RSB + c0s*16, pAh + (size_t)(row0+r0s)*ldka + k0 + c0s*8);
        cpasync16(base          + r1s*RSB + c1s*16, pAh + (size_t)(row0+r1s)*ldka + k0 + c1s*8);
        cpasync16(base +   ARRB + r0s*RSB + c0s*16, pAl + (size_t)(row0+r0s)*ldka + k0 + c0s*8);
        cpasync16(base +   ARRB + r1s*RSB + c1s*16, pAl + (size_t)(row0+r1s)*ldka + k0 + c1s*8);
        cpasync16(base + 2*ARRB + r0s*RSB + c0s*16, pBh + (size_t)(col0+r0s)*ldkb + k0 + c0s*8);
        cpasync16(base + 2*ARRB + r1s*RSB + c1s*16, pBh + (size_t)(col0+r1s)*ldkb + k0 + c1s*8);
        cpasync16(base + 3*ARRB + r0s*RSB + c0s*16, pBl + (size_t)(col0+r0s)*ldkb + k0 + c0s*8);
        cpasync16(base + 3*ARRB + r1s*RSB + c1s*16, pBl + (size_t)(col0+r1s)*ldkb + k0 + c1s*8);
    };

    float acc[4][4][4] = {};

    stage(0, 0); CP_COMMIT();
    const int nc = K / 32;
    for (int c = 0; c < nc; c++) {
        const int buf = c & 1;
        if (c + 1 < nc) { stage(c + 1, buf ^ 1); CP_COMMIT(); cp_wait<1>(); }
        else            { cp_wait<0>(); }
        __syncthreads();

        const uint32_t aB = sb + buf * BUFB;
        #pragma unroll
        for (int kk = 0; kk < 2; kk++) {
            const uint32_t kb = kk * 32 + tig * 4;
            // B fragments once per k16 (hi and lo)
            uint32_t bh[4][2], bl[4][2];
            #pragma unroll
            for (int nt = 0; nt < 4; nt++) {
                uint32_t rb = aB + 2*ARRB + (uint32_t)(wn + nt*8 + g) * RSB + kb;
                bh[nt][0] = lds32(rb);          bh[nt][1] = lds32(rb + 16);
                bl[nt][0] = lds32(rb + ARRB);   bl[nt][1] = lds32(rb + ARRB + 16);
            }
            #pragma unroll
            for (int mt = 0; mt < 4; mt++) {
                uint32_t ra = aB + (uint32_t)(wm + mt*16 + g) * RSB + kb;
                uint32_t ah[4], al[4];
                ah[0] = lds32(ra);        ah[1] = lds32(ra + 8*RSB);
                ah[2] = lds32(ra + 16);   ah[3] = lds32(ra + 8*RSB + 16);
                al[0] = lds32(ra + ARRB);      al[1] = lds32(ra + ARRB + 8*RSB);
                al[2] = lds32(ra + ARRB + 16); al[3] = lds32(ra + ARRB + 8*RSB + 16);
                #pragma unroll
                for (int nt = 0; nt < 4; nt++) {
                    mma_bf16(acc[mt][nt], ah, bh[nt]);
                    mma_bf16(acc[mt][nt], ah, bl[nt]);
                    mma_bf16(acc[mt][nt], al, bh[nt]);
                }
            }
        }
        __syncthreads();
    }

    // ---- epilogue ----------------------------------------------------------
    #pragma unroll
    for (int mt = 0; mt < 4; mt++) {
        const int r_lo = row0 + wm + mt*16 + g;
        const int r_hi = r_lo + 8;
        if (EPI == 1) {
            #pragma unroll
            for (int nt = 0; nt < 4; nt++) {
                const int cc = col0 + wn + nt*8 + tig*2;
                float v0 = (cc   < Nv) ? fmaxf(acc[mt][nt][0] + P1[cc],   0.f) : 0.f;
                float v1 = (cc+1 < Nv) ? fmaxf(acc[mt][nt][1] + P1[cc+1], 0.f) : 0.f;
                float v2 = (cc   < Nv) ? fmaxf(acc[mt][nt][2] + P1[cc],   0.f) : 0.f;
                float v3 = (cc+1 < Nv) ? fmaxf(acc[mt][nt][3] + P1[cc+1], 0.f) : 0.f;
                __nv_bfloat16 h0 = __float2bfloat16(v0), h1 = __float2bfloat16(v1);
                __nv_bfloat16 h2 = __float2bfloat16(v2), h3 = __float2bfloat16(v3);
                __nv_bfloat162 hv0; hv0.x = h0; hv0.y = h1;
                __nv_bfloat162 hv1; hv1.x = h2; hv1.y = h3;
                __nv_bfloat162 lv0; lv0.x = __float2bfloat16(v0 - __bfloat162float(h0));
                                    lv0.y = __float2bfloat16(v1 - __bfloat162float(h1));
                __nv_bfloat162 lv1; lv1.x = __float2bfloat16(v2 - __bfloat162float(h2));
                                    lv1.y = __float2bfloat16(v3 - __bfloat162float(h3));
                *reinterpret_cast<__nv_bfloat162*>(Oh + (size_t)r_lo * ldc + cc) = hv0;
                *reinterpret_cast<__nv_bfloat162*>(Oh + (size_t)r_hi * ldc + cc) = hv1;
                *reinterpret_cast<__nv_bfloat162*>(Ol + (size_t)r_lo * ldc + cc) = lv0;
                *reinterpret_cast<__nv_bfloat162*>(Ol + (size_t)r_hi * ldc + cc) = lv1;
            }
        } else {
            float s_lo = 1.f, s_hi = 1.f;
            if (EPI == 2) {
                s_lo = P1[b*LL + r_lo] * P2[b*LL + r_lo];
                s_hi = P1[b*LL + r_hi] * P2[b*LL + r_hi];
            }
            float* C0 = Cg + (size_t)b * sC + (size_t)r_lo * ldc;
            float* C1 = Cg + (size_t)b * sC + (size_t)r_hi * ldc;
            #pragma unroll
            for (int nt = 0; nt < 4; nt++) {
                const int cc = col0 + wn + nt*8 + tig*2;
                if (cc < Nv) {
                    *reinterpret_cast<float2*>(C0 + cc) =
                        make_float2(acc[mt][nt][0] * s_lo, acc[mt][nt][1] * s_lo);
                    *reinterpret_cast<float2*>(C1 + cc) =
                        make_float2(acc[mt][nt][2] * s_hi, acc[mt][nt][3] * s_hi);
                }
            }
        }
    }
}

// ---------------------------------------------------------------------------
// W [K][N] fp32 -> W^T bf16 hi/lo pairs [NP][KP], zero-padded.
// grid (KP/32, NP/32), block 256.
// ---------------------------------------------------------------------------
__global__ __launch_bounds__(256)
void k_wsplit(const float* __restrict__ W,
              __nv_bfloat16* __restrict__ Th, __nv_bfloat16* __restrict__ Tl,
              int K, int N, int KP)
{
    __shared__ float tile[32][33];
    int k0 = blockIdx.x * 32;
    int n0 = blockIdx.y * 32;
    int tx = threadIdx.x & 31, ty = threadIdx.x >> 5;
    #pragma unroll
    for (int i = 0; i < 4; i++) {
        int k = k0 + ty + i * 8, n = n0 + tx;
        tile[ty + i * 8][tx] = (k < K && n < N) ? W[(size_t)k * N + n] : 0.f;
    }
    __syncthreads();
    #pragma unroll
    for (int i = 0; i < 4; i++) {
        int n = n0 + ty + i * 8, k = k0 + tx;
        float v = tile[tx][ty + i * 8];
        __nv_bfloat16 hi = __float2bfloat16(v);
        size_t o = (size_t)n * KP + k;
        Th[o] = hi;
        Tl[o] = __float2bfloat16(v - __bfloat162float(hi));
    }
}

// ---------------------------------------------------------------------------
// s [b][l][d] fp32 -> transposed pairs [b][DP][LL] AND natural pairs [b][l][DP]
// ---------------------------------------------------------------------------
__global__ __launch_bounds__(256)
void k_split_transpose(const float* __restrict__ S,
                       __nv_bfloat16* __restrict__ Th, __nv_bfloat16* __restrict__ Tl,
                       __nv_bfloat16* __restrict__ Nh, __nv_bfloat16* __restrict__ Nl)
{
    __shared__ float tile[32][33];
    int b  = blockIdx.z;
    int l0 = blockIdx.x * 32;
    int d0 = blockIdx.y * 32;
    int tx = threadIdx.x & 31, ty = threadIdx.x >> 5;
    #pragma unroll
    for (int i = 0; i < 4; i++) {
        int l = l0 + ty + i * 8, d = d0 + tx;
        float v = (d < NI) ? S[((size_t)b * LL + l) * NI + d] : 0.f;
        tile[ty + i * 8][tx] = v;
        __nv_bfloat16 hi = __float2bfloat16(v);
        size_t o = ((size_t)b * LL + l) * DP + d;       // natural pairs
        Nh[o] = hi;
        Nl[o] = __float2bfloat16(v - __bfloat162float(hi));
    }
    __syncthreads();
    #pragma unroll
    for (int i = 0; i < 4; i++) {
        int d = d0 + ty + i * 8;
        float v = tile[tx][ty + i * 8];
        __nv_bfloat16 hi = __float2bfloat16(v);
        size_t o = ((size_t)b * DP + d) * LL + l0 + tx; // transposed pairs
        Th[o] = hi;
        Tl[o] = __float2bfloat16(v - __bfloat162float(hi));
    }
}

// ---------------------------------------------------------------------------
// Alpha softmax over l per column m: unnormalized exp TRANSPOSED -> g_eah/l,
// 1/sum -> g_ia. logit = e[l,m]*mask1[b,l].
// ---------------------------------------------------------------------------
__global__ __launch_bounds__(256)
void k_softmax_cols(const float* __restrict__ mask1) {
    int b  = blockIdx.y;
    int m0 = blockIdx.x * 32;
    int tx = threadIdx.x & 31, ty = threadIdx.x >> 5;
    const float* pe = g_e + (size_t)b * LL * LL;
    __shared__ float smk[LL];
    __shared__ float red[8][33];
    __shared__ float tile[32][33];
    for (int l = threadIdx.x; l < LL; l += 256) smk[l] = mask1[b * LL + l];
    __syncthreads();

    float mx = -3.4e38f;
    for (int l = ty; l < LL; l += 8)
        mx = fmaxf(mx, pe[(size_t)l * LL + m0 + tx] * smk[l]);
    red[ty][tx] = mx;
    __syncthreads();
    mx = red[0][tx];
    #pragma unroll
    for (int j = 1; j < 8; j++) mx = fmaxf(mx, red[j][tx]);

    float sum = 0.f;
    for (int l0 = 0; l0 < LL; l0 += 32) {
        #pragma unroll
        for (int i = 0; i < 4; i++) {
            int lo = ty * 4 + i;
            int l  = l0 + lo;
            float t = __expf(pe[(size_t)l * LL + m0 + tx] * smk[l] - mx);
            sum += t;
            tile[tx][lo] = t;
        }
        __syncthreads();
        #pragma unroll
        for (int i = 0; i < 4; i++) {
            int m = ty * 4 + i;
            float t = tile[m][tx];
            __nv_bfloat16 hi = __float2bfloat16(t);
            size_t o = ((size_t)b * LL + m0 + m) * LL + l0 + tx;
            g_eah[o] = hi;
            g_eal[o] = __float2bfloat16(t - __bfloat162float(hi));
        }
        __syncthreads();
    }
    red[ty][tx] = sum;
    __syncthreads();
    if (ty == 0) {
        float s = 0.f;
        #pragma unroll
        for (int j = 0; j < 8; j++) s += red[j][tx];
        g_ia[b * LL + m0 + tx] = 1.f / s;
    }
}

// ---------------------------------------------------------------------------
// Beta softmax over m per row l: unnormalized exp -> g_ebh/l, 1/sum -> g_ib.
// ---------------------------------------------------------------------------
__global__ __launch_bounds__(256)
void k_softmax_rows(const float* __restrict__ mask2) {
    int row = blockIdx.x;
    int b = row >> 10;
    const float* p = g_e + (size_t)row * LL;
    const float* mk = mask2 + b * LL;
    int tid = threadIdx.x;
    __shared__ float red[256];
    float v[4];
    float mx = -3.4e38f;
    #pragma unroll
    for (int i = 0; i < 4; i++) {
        int m = tid + i * 256;
        v[i] = p[m] * mk[m];
        mx = fmaxf(mx, v[i]);
    }
    red[tid] = mx; __syncthreads();
    for (int s = 128; s > 0; s >>= 1) {
        if (tid < s) red[tid] = fmaxf(red[tid], red[tid + s]);
        __syncthreads();
    }
    mx = red[0]; __syncthreads();
    float sum = 0.f;
    #pragma unroll
    for (int i = 0; i < 4; i++) { v[i] = __expf(v[i] - mx); sum += v[i]; }
    red[tid] = sum; __syncthreads();
    for (int s = 128; s > 0; s >>= 1) {
        if (tid < s) red[tid] += red[tid + s];
        __syncthreads();
    }
    float total = red[0];
    #pragma unroll
    for (int i = 0; i < 4; i++) {
        int m = tid + i * 256;
        __nv_bfloat16 hi = __float2bfloat16(v[i]);
        g_ebh[(size_t)row * LL + m] = hi;
        g_ebl[(size_t)row * LL + m] = __float2bfloat16(v[i] - __bfloat162float(hi));
    }
    if (tid == 0) g_ib[row] = 1.f / total;
}

// ---------------------------------------------------------------------------
extern "C" void kernel_launch(void* const* d_in, const int* in_sizes, int n_in,
                              void* d_out, int out_size) {
    const float* s1    = (const float*)d_in[0];
    const float* s2    = (const float*)d_in[1];
    const float* mask1 = (const float*)d_in[2];
    const float* mask2 = (const float*)d_in[3];
    const float* W1    = (const float*)d_in[4];
    const float* b1    = (const float*)d_in[5];
    const float* W2    = (const float*)d_in[6];
    const float* b2    = (const float*)d_in[7];
    float* out       = (float*)d_out;
    float* out_alpha = out;
    float* out_beta  = out + (size_t)NB*LL*NI;

    float *p_e, *p_ia, *p_ib;
    __nv_bfloat16 *p_tph, *p_tpl, *p_h1h, *p_h1l, *p_h2h, *p_h2l;
    __nv_bfloat16 *p_eah, *p_eal, *p_ebh, *p_ebl;
    __nv_bfloat16 *p_s1h, *p_s1l, *p_s2h, *p_s2l;
    __nv_bfloat16 *p_s1ph, *p_s1pl, *p_s2ph, *p_s2pl;
    __nv_bfloat16 *p_w1th, *p_w1tl, *p_w2th, *p_w2tl;
    cudaGetSymbolAddress((void**)&p_e,    g_e);
    cudaGetSymbolAddress((void**)&p_ia,   g_ia);
    cudaGetSymbolAddress((void**)&p_ib,   g_ib);
    cudaGetSymbolAddress((void**)&p_tph,  g_tph);
    cudaGetSymbolAddress((void**)&p_tpl,  g_tpl);
    cudaGetSymbolAddress((void**)&p_h1h,  g_h1h);
    cudaGetSymbolAddress((void**)&p_h1l,  g_h1l);
    cudaGetSymbolAddress((void**)&p_h2h,  g_h2h);
    cudaGetSymbolAddress((void**)&p_h2l,  g_h2l);
    cudaGetSymbolAddress((void**)&p_eah,  g_eah);
    cudaGetSymbolAddress((void**)&p_eal,  g_eal);
    cudaGetSymbolAddress((void**)&p_ebh,  g_ebh);
    cudaGetSymbolAddress((void**)&p_ebl,  g_ebl);
    cudaGetSymbolAddress((void**)&p_s1h,  g_s1h);
    cudaGetSymbolAddress((void**)&p_s1l,  g_s1l);
    cudaGetSymbolAddress((void**)&p_s2h,  g_s2h);
    cudaGetSymbolAddress((void**)&p_s2l,  g_s2l);
    cudaGetSymbolAddress((void**)&p_s1ph, g_s1ph);
    cudaGetSymbolAddress((void**)&p_s1pl, g_s1pl);
    cudaGetSymbolAddress((void**)&p_s2ph, g_s2ph);
    cudaGetSymbolAddress((void**)&p_s2pl, g_s2pl);
    cudaGetSymbolAddress((void**)&p_w1th, g_w1th);
    cudaGetSymbolAddress((void**)&p_w1tl, g_w1tl);
    cudaGetSymbolAddress((void**)&p_w2th, g_w2th);
    cudaGetSymbolAddress((void**)&p_w2tl, g_w2tl);

    const int MMA_SMEM = 2 * BUFB;   // 81920
    cudaFuncSetAttribute(gemm_mma<0>, cudaFuncAttributeMaxDynamicSharedMemorySize, MMA_SMEM);
    cudaFuncSetAttribute(gemm_mma<1>, cudaFuncAttributeMaxDynamicSharedMemorySize, MMA_SMEM);
    cudaFuncSetAttribute(gemm_mma<2>, cudaFuncAttributeMaxDynamicSharedMemorySize, MMA_SMEM);

    dim3 blk(256);

    // 1-2: W1^T, W2^T splits (tiny)
    k_wsplit<<<dim3(DP/32, 256/32), blk>>>(W1, p_w1th, p_w1tl, NI, NH, DP);
    k_wsplit<<<dim3(KH/32, 256/32), blk>>>(W2, p_w2th, p_w2tl, NH, NH, KH);

    // 3-4: s splits (transposed for beta/alpha B, natural for MLP A)
    {
        dim3 gt(LL / 32, DP / 32, NB);
        k_split_transpose<<<gt, blk>>>(s1, p_s1h, p_s1l, p_s1ph, p_s1pl);
        k_split_transpose<<<gt, blk>>>(s2, p_s2h, p_s2l, p_s2ph, p_s2pl);
    }

    // 5-8: MLP on tensor cores (K=640 then K=256), bf16-pair outputs
    {
        dim3 g1(2, NR / 128, 1);   // N=256 padded
        gemm_mma<1><<<g1, blk, MMA_SMEM>>>(p_s1ph, p_s1pl, p_w1th, p_w1tl,
                                           b1, nullptr, nullptr, p_tph, p_tpl,
                                           DP, DP, DP, KH, NH, 0, 0, 0);
        gemm_mma<1><<<g1, blk, MMA_SMEM>>>(p_tph, p_tpl, p_w2th, p_w2tl,
                                           b2, nullptr, nullptr, p_h1h, p_h1l,
                                           KH, KH, KH, KH, NH, 0, 0, 0);
        gemm_mma<1><<<g1, blk, MMA_SMEM>>>(p_s2ph, p_s2pl, p_w1th, p_w1tl,
                                           b1, nullptr, nullptr, p_tph, p_tpl,
                                           DP, DP, DP, KH, NH, 0, 0, 0);
        gemm_mma<1><<<g1, blk, MMA_SMEM>>>(p_tph, p_tpl, p_w2th, p_w2tl,
                                           b2, nullptr, nullptr, p_h2h, p_h2l,
                                           KH, KH, KH, KH, NH, 0, 0, 0);
    }

    // 9: e[b,l,m] = h1 . h2
    {
        dim3 ge(LL / 128, LL / 128, NB);
        gemm_mma<0><<<ge, blk, MMA_SMEM>>>(p_h1h, p_h1l, p_h2h, p_h2l,
                                           nullptr, nullptr, p_e, nullptr, nullptr,
                                           KH, KH, KH, LL, LL,
                                           (size_t)LL*KH, (size_t)LL*KH, (size_t)LL*LL);
    }

    // 10-11: softmaxes
    {
        dim3 gs(LL / 32, NB);
        k_softmax_cols<<<gs, blk>>>(mask1);
    }
    k_softmax_rows<<<NR, blk>>>(mask2);

    // 12-13: alphas / betas
    {
        dim3 ga(DP / 128, LL / 128, NB);
        gemm_mma<2><<<ga, blk, MMA_SMEM>>>(p_eah, p_eal, p_s1h, p_s1l,
                                           p_ia, mask2, out_alpha, nullptr, nullptr,
                                           LL, LL, LL, NI, NI,
                                           (size_t)LL*LL, (size_t)DP*LL, (size_t)LL*NI);
        gemm_mma<2><<<ga, blk, MMA_SMEM>>>(p_ebh, p_ebl, p_s2h, p_s2l,
                                           p_ib, mask1, out_beta, nullptr, nullptr,
                                           LL, LL, LL, NI, NI,
                                           (size_t)LL*LL, (size_t)DP*LL, (size_t)LL*NI);
    }
}

// round 17
// speedup vs baseline: 2.5619x; 1.1216x over previous
#include <cuda_runtime.h>
#include <cuda_bf16.h>
#include <math.h>
#include <cstdint>

#define NB 32
#define LL 1024
#define NI 600
#define NH 200
#define NR (NB*LL)
#define KH 256      // padded K stride for h/t pairs (200 -> 256)
#define KHE 224     // effective K for h/t (200 -> 224, mult of 32)
#define DP 640      // padded d stride (600 -> 640)
#define DPE 608     // effective K over d (600 -> 608, mult of 32)

// ---------------- scratch (device globals; no runtime allocation) ----------
__device__ __align__(16) __nv_bfloat16 g_tph[(size_t)NR*KH];    // MLP L1 out pairs
__device__ __align__(16) __nv_bfloat16 g_tpl[(size_t)NR*KH];
__device__ __align__(16) __nv_bfloat16 g_h1h[(size_t)NR*KH];
__device__ __align__(16) __nv_bfloat16 g_h1l[(size_t)NR*KH];
__device__ __align__(16) __nv_bfloat16 g_h2h[(size_t)NR*KH];
__device__ __align__(16) __nv_bfloat16 g_h2l[(size_t)NR*KH];
__device__ __align__(16) float g_e [(size_t)NB*LL*LL];
__device__ __align__(16) __nv_bfloat16 g_eah[(size_t)NB*LL*LL]; // exp_a^T [b][m][l]
__device__ __align__(16) __nv_bfloat16 g_eal[(size_t)NB*LL*LL];
__device__ __align__(16) __nv_bfloat16 g_ebh[(size_t)NB*LL*LL]; // exp_b [b][l][m]
__device__ __align__(16) __nv_bfloat16 g_ebl[(size_t)NB*LL*LL];
__device__ __align__(16) __nv_bfloat16 g_s1h[(size_t)NB*DP*LL]; // s1^T [b][d][l]
__device__ __align__(16) __nv_bfloat16 g_s1l[(size_t)NB*DP*LL];
__device__ __align__(16) __nv_bfloat16 g_s2h[(size_t)NB*DP*LL];
__device__ __align__(16) __nv_bfloat16 g_s2l[(size_t)NB*DP*LL];
__device__ __align__(16) __nv_bfloat16 g_s1ph[(size_t)NR*DP];   // s1 [b][l][d] pairs
__device__ __align__(16) __nv_bfloat16 g_s1pl[(size_t)NR*DP];
__device__ __align__(16) __nv_bfloat16 g_s2ph[(size_t)NR*DP];
__device__ __align__(16) __nv_bfloat16 g_s2pl[(size_t)NR*DP];
__device__ __align__(16) __nv_bfloat16 g_w1th[256*DP];          // W1^T pairs [256][640]
__device__ __align__(16) __nv_bfloat16 g_w1tl[256*DP];
__device__ __align__(16) __nv_bfloat16 g_w2th[256*KH];          // W2^T pairs [256][256]
__device__ __align__(16) __nv_bfloat16 g_w2tl[256*KH];
__device__ float g_ia[NR];
__device__ float g_ib[NR];

// ======================= low-level helpers (sm_80-safe PTX only) ===========
static __device__ __forceinline__ uint32_t smem_u32(const void* p) {
    uint32_t a;
    asm("{ .reg .u64 t; cvta.to.shared.u64 t, %1; cvt.u32.u64 %0, t; }" : "=r"(a) : "l"(p));
    return a;
}
static __device__ __forceinline__ void ldsm4(uint32_t* r, uint32_t addr) {
    asm volatile("ldmatrix.sync.aligned.m8n8.x4.shared.b16 {%0,%1,%2,%3}, [%4];"
        : "=r"(r[0]), "=r"(r[1]), "=r"(r[2]), "=r"(r[3]) : "r"(addr));
}
static __device__ __forceinline__ void cpasync16(uint32_t s, const void* g) {
    asm volatile("cp.async.cg.shared.global [%0], [%1], 16;" :: "r"(s), "l"(g) : "memory");
}
#define CP_COMMIT() asm volatile("cp.async.commit_group;" ::: "memory")
template<int N> static __device__ __forceinline__ void cp_wait() {
    asm volatile("cp.async.wait_group %0;" :: "n"(N) : "memory");
}
static __device__ __forceinline__ void mma_bf16(float* d, const uint32_t* a, const uint32_t* b) {
    asm volatile(
        "mma.sync.aligned.m16n8k16.row.col.f32.bf16.bf16.f32 "
        "{%0,%1,%2,%3}, {%4,%5,%6,%7}, {%8,%9}, {%0,%1,%2,%3};"
        : "+f"(d[0]), "+f"(d[1]), "+f"(d[2]), "+f"(d[3])
        : "r"(a[0]), "r"(a[1]), "r"(a[2]), "r"(a[3]), "r"(b[0]), "r"(b[1]));
}

// ---------------------------------------------------------------------------
// Tensor GEMM via mma.sync: C[r][n] = sum_k A[r][k]*B[n][k], bf16 hi/lo split
// (3 MMAs: AhBh + AhBl + AlBh), fp32 accum. ldmatrix fragment loads; split
// loops reordered so same-acc MMAs are 4 apart (RAW-latency hiding).
// CTA tile 128x128, K-chunk 32, cp.async double-buffered. Rows 80B.
//   EPI 0: Cg = acc (fp32)
//   EPI 1: Oh/Ol = bf16 hi/lo of relu(acc + P1[c]) (0 for c>=Nv)
//   EPI 2: Cg = acc * P1[b*LL+r] * P2[b*LL+r]   (guard c<Nv)
// ---------------------------------------------------------------------------
#define RSB  80                 // smem row stride (bytes): 32 bf16 + pad
#define ARRB (128*RSB)          // one array (10240 B)
#define BUFB (4*ARRB)           // Ah,Al,Bh,Bl per buffer (40960 B)

template<int EPI>
__global__ __launch_bounds__(256, 2)
void gemm_mma(const __nv_bfloat16* __restrict__ Ah, const __nv_bfloat16* __restrict__ Al,
              const __nv_bfloat16* __restrict__ Bh, const __nv_bfloat16* __restrict__ Bl,
              const float* __restrict__ P1, const float* __restrict__ P2,
              float* __restrict__ Cg,
              __nv_bfloat16* __restrict__ Oh, __nv_bfloat16* __restrict__ Ol,
              int K, int ldka, int ldkb, int ldc, int Nv,
              size_t sA, size_t sB, size_t sC)
{
    extern __shared__ __align__(16) char smem[];
    const int b    = blockIdx.z;
    const int row0 = blockIdx.y * 128;
    const int col0 = blockIdx.x * 128;
    const __nv_bfloat16* pAh = Ah + (size_t)b * sA;
    const __nv_bfloat16* pAl = Al + (size_t)b * sA;
    const __nv_bfloat16* pBh = Bh + (size_t)b * sB;
    const __nv_bfloat16* pBl = Bl + (size_t)b * sB;

    const uint32_t sb = smem_u32(smem);
    const int tid  = threadIdx.x;
    const int wid  = tid >> 5;
    const int lane = tid & 31;
    const int wm   = (wid & 1) * 64;
    const int wn   = (wid >> 1) * 32;
    const int g    = lane >> 2;
    const int tig  = lane & 3;

    // ldmatrix per-lane address offsets (q = lane>>3)
    const int li = lane & 7;
    // A x4: q0: rows+0 k0 | q1: rows+8 k0 | q2: rows+0 k16B | q3: rows+8 k16B
    const uint32_t aoffA = (uint32_t)(wm + ((lane >> 3) & 1) * 8 + li) * RSB
                         + (uint32_t)(lane >> 4) * 16;
    // B x4 (nt pair j): q0: nt(2j) k0 | q1: nt(2j) k16B | q2: nt(2j+1) k0 | q3: nt(2j+1) k16B
    const uint32_t aoffB = (uint32_t)(wn + (lane >> 4) * 8 + li) * RSB
                         + (uint32_t)((lane >> 3) & 1) * 16;

    const int r0s = tid >> 2,         c0s = tid & 3;
    const int r1s = (tid + 256) >> 2, c1s = (tid + 256) & 3;

    auto stage = [&](int kc, int buf) {
        const uint32_t base = sb + buf * BUFB;
        const int k0 = kc * 32;
        cpasync16(base          + r0s*RSB + c0s*16, pAh + (size_t)(row0+r0s)*ldka + k0 + c0s*8);
        cpasync16(base          + r1s*RSB + c1s*16, pAh + (size_t)(row0+r1s)*ldka + k0 + c1s*8);
        cpasync16(base +   ARRB + r0s*RSB + c0s*16, pAl + (size_t)(row0+r0s)*ldka + k0 + c0s*8);
        cpasync16(base +   ARRB + r1s*RSB + c1s*16, pAl + (size_t)(row0+r1s)*ldka + k0 + c1s*8);
        cpasync16(base + 2*ARRB + r0s*RSB + c0s*16, pBh + (size_t)(col0+r0s)*ldkb + k0 + c0s*8);
        cpasync16(base + 2*ARRB + r1s*RSB + c1s*16, pBh + (size_t)(col0+r1s)*ldkb + k0 + c1s*8);
        cpasync16(base + 3*ARRB + r0s*RSB + c0s*16, pBl + (size_t)(col0+r0s)*ldkb + k0 + c0s*8);
        cpasync16(base + 3*ARRB + r1s*RSB + c1s*16, pBl + (size_t)(col0+r1s)*ldkb + k0 + c1s*8);
    };

    float acc[4][4][4] = {};

    stage(0, 0); CP_COMMIT();
    const int nc = K / 32;
    for (int c = 0; c < nc; c++) {
        const int buf = c & 1;
        if (c + 1 < nc) { stage(c + 1, buf ^ 1); CP_COMMIT(); cp_wait<1>(); }
        else            { cp_wait<0>(); }
        __syncthreads();

        const uint32_t aB = sb + buf * BUFB;
        #pragma unroll
        for (int kk = 0; kk < 2; kk++) {
            const uint32_t kb = kk * 32;
            // B fragments once per k16 (hi and lo), via 4x ldmatrix.x4
            uint32_t bh[4][2], bl[4][2], t[4];
            #pragma unroll
            for (int j = 0; j < 2; j++) {
                ldsm4(t, aB + 2*ARRB + aoffB + (uint32_t)j * (16*RSB) + kb);
                bh[2*j][0] = t[0]; bh[2*j][1] = t[1]; bh[2*j+1][0] = t[2]; bh[2*j+1][1] = t[3];
                ldsm4(t, aB + 3*ARRB + aoffB + (uint32_t)j * (16*RSB) + kb);
                bl[2*j][0] = t[0]; bl[2*j][1] = t[1]; bl[2*j+1][0] = t[2]; bl[2*j+1][1] = t[3];
            }
            #pragma unroll
            for (int mt = 0; mt < 4; mt++) {
                uint32_t ah[4], al[4];
                ldsm4(ah, aB        + aoffA + (uint32_t)mt * (16*RSB) + kb);
                ldsm4(al, aB + ARRB + aoffA + (uint32_t)mt * (16*RSB) + kb);
                // split-major order: same acc re-written only every 4 MMAs
                #pragma unroll
                for (int nt = 0; nt < 4; nt++) mma_bf16(acc[mt][nt], ah, bh[nt]);
                #pragma unroll
                for (int nt = 0; nt < 4; nt++) mma_bf16(acc[mt][nt], ah, bl[nt]);
                #pragma unroll
                for (int nt = 0; nt < 4; nt++) mma_bf16(acc[mt][nt], al, bh[nt]);
            }
        }
        __syncthreads();
    }

    // ---- epilogue ----------------------------------------------------------
    #pragma unroll
    for (int mt = 0; mt < 4; mt++) {
        const int r_lo = row0 + wm + mt*16 + g;
        const int r_hi = r_lo + 8;
        if (EPI == 1) {
            #pragma unroll
            for (int nt = 0; nt < 4; nt++) {
                const int cc = col0 + wn + nt*8 + tig*2;
                float v0 = (cc   < Nv) ? fmaxf(acc[mt][nt][0] + P1[cc],   0.f) : 0.f;
                float v1 = (cc+1 < Nv) ? fmaxf(acc[mt][nt][1] + P1[cc+1], 0.f) : 0.f;
                float v2 = (cc   < Nv) ? fmaxf(acc[mt][nt][2] + P1[cc],   0.f) : 0.f;
                float v3 = (cc+1 < Nv) ? fmaxf(acc[mt][nt][3] + P1[cc+1], 0.f) : 0.f;
                __nv_bfloat16 h0 = __float2bfloat16(v0), h1 = __float2bfloat16(v1);
                __nv_bfloat16 h2 = __float2bfloat16(v2), h3 = __float2bfloat16(v3);
                __nv_bfloat162 hv0; hv0.x = h0; hv0.y = h1;
                __nv_bfloat162 hv1; hv1.x = h2; hv1.y = h3;
                __nv_bfloat162 lv0; lv0.x = __float2bfloat16(v0 - __bfloat162float(h0));
                                    lv0.y = __float2bfloat16(v1 - __bfloat162float(h1));
                __nv_bfloat162 lv1; lv1.x = __float2bfloat16(v2 - __bfloat162float(h2));
                                    lv1.y = __float2bfloat16(v3 - __bfloat162float(h3));
                *reinterpret_cast<__nv_bfloat162*>(Oh + (size_t)r_lo * ldc + cc) = hv0;
                *reinterpret_cast<__nv_bfloat162*>(Oh + (size_t)r_hi * ldc + cc) = hv1;
                *reinterpret_cast<__nv_bfloat162*>(Ol + (size_t)r_lo * ldc + cc) = lv0;
                *reinterpret_cast<__nv_bfloat162*>(Ol + (size_t)r_hi * ldc + cc) = lv1;
            }
        } else {
            float s_lo = 1.f, s_hi = 1.f;
            if (EPI == 2) {
                s_lo = P1[b*LL + r_lo] * P2[b*LL + r_lo];
                s_hi = P1[b*LL + r_hi] * P2[b*LL + r_hi];
            }
            float* C0 = Cg + (size_t)b * sC + (size_t)r_lo * ldc;
            float* C1 = Cg + (size_t)b * sC + (size_t)r_hi * ldc;
            #pragma unroll
            for (int nt = 0; nt < 4; nt++) {
                const int cc = col0 + wn + nt*8 + tig*2;
                if (cc < Nv) {
                    *reinterpret_cast<float2*>(C0 + cc) =
                        make_float2(acc[mt][nt][0] * s_lo, acc[mt][nt][1] * s_lo);
                    *reinterpret_cast<float2*>(C1 + cc) =
                        make_float2(acc[mt][nt][2] * s_hi, acc[mt][nt][3] * s_hi);
                }
            }
        }
    }
}

// ---------------------------------------------------------------------------
// W [K][N] fp32 -> W^T bf16 hi/lo pairs [NP][KP], zero-padded.
// ---------------------------------------------------------------------------
__global__ __launch_bounds__(256)
void k_wsplit(const float* __restrict__ W,
              __nv_bfloat16* __restrict__ Th, __nv_bfloat16* __restrict__ Tl,
              int K, int N, int KP)
{
    __shared__ float tile[32][33];
    int k0 = blockIdx.x * 32;
    int n0 = blockIdx.y * 32;
    int tx = threadIdx.x & 31, ty = threadIdx.x >> 5;
    #pragma unroll
    for (int i = 0; i < 4; i++) {
        int k = k0 + ty + i * 8, n = n0 + tx;
        tile[ty + i * 8][tx] = (k < K && n < N) ? W[(size_t)k * N + n] : 0.f;
    }
    __syncthreads();
    #pragma unroll
    for (int i = 0; i < 4; i++) {
        int n = n0 + ty + i * 8, k = k0 + tx;
        float v = tile[tx][ty + i * 8];
        __nv_bfloat16 hi = __float2bfloat16(v);
        size_t o = (size_t)n * KP + k;
        Th[o] = hi;
        Tl[o] = __float2bfloat16(v - __bfloat162float(hi));
    }
}

// ---------------------------------------------------------------------------
// s [b][l][d] fp32 -> transposed pairs [b][DP][LL] AND natural pairs [b][l][DP]
// ---------------------------------------------------------------------------
__global__ __launch_bounds__(256)
void k_split_transpose(const float* __restrict__ S,
                       __nv_bfloat16* __restrict__ Th, __nv_bfloat16* __restrict__ Tl,
                       __nv_bfloat16* __restrict__ Nh, __nv_bfloat16* __restrict__ Nl)
{
    __shared__ float tile[32][33];
    int b  = blockIdx.z;
    int l0 = blockIdx.x * 32;
    int d0 = blockIdx.y * 32;
    int tx = threadIdx.x & 31, ty = threadIdx.x >> 5;
    #pragma unroll
    for (int i = 0; i < 4; i++) {
        int l = l0 + ty + i * 8, d = d0 + tx;
        float v = (d < NI) ? S[((size_t)b * LL + l) * NI + d] : 0.f;
        tile[ty + i * 8][tx] = v;
        __nv_bfloat16 hi = __float2bfloat16(v);
        size_t o = ((size_t)b * LL + l) * DP + d;       // natural pairs
        Nh[o] = hi;
        Nl[o] = __float2bfloat16(v - __bfloat162float(hi));
    }
    __syncthreads();
    #pragma unroll
    for (int i = 0; i < 4; i++) {
        int d = d0 + ty + i * 8;
        float v = tile[tx][ty + i * 8];
        __nv_bfloat16 hi = __float2bfloat16(v);
        size_t o = ((size_t)b * DP + d) * LL + l0 + tx; // transposed pairs
        Th[o] = hi;
        Tl[o] = __float2bfloat16(v - __bfloat162float(hi));
    }
}

// ---------------------------------------------------------------------------
// Alpha softmax over l per column m: unnormalized exp TRANSPOSED -> g_eah/l,
// 1/sum -> g_ia. logit = e[l,m]*mask1[b,l].
// ---------------------------------------------------------------------------
__global__ __launch_bounds__(256)
void k_softmax_cols(const float* __restrict__ mask1) {
    int b  = blockIdx.y;
    int m0 = blockIdx.x * 32;
    int tx = threadIdx.x & 31, ty = threadIdx.x >> 5;
    const float* pe = g_e + (size_t)b * LL * LL;
    __shared__ float smk[LL];
    __shared__ float red[8][33];
    __shared__ float tile[32][33];
    for (int l = threadIdx.x; l < LL; l += 256) smk[l] = mask1[b * LL + l];
    __syncthreads();

    float mx = -3.4e38f;
    for (int l = ty; l < LL; l += 8)
        mx = fmaxf(mx, pe[(size_t)l * LL + m0 + tx] * smk[l]);
    red[ty][tx] = mx;
    __syncthreads();
    mx = red[0][tx];
    #pragma unroll
    for (int j = 1; j < 8; j++) mx = fmaxf(mx, red[j][tx]);

    float sum = 0.f;
    for (int l0 = 0; l0 < LL; l0 += 32) {
        #pragma unroll
        for (int i = 0; i < 4; i++) {
            int lo = ty * 4 + i;
            int l  = l0 + lo;
            float t = __expf(pe[(size_t)l * LL + m0 + tx] * smk[l] - mx);
            sum += t;
            tile[tx][lo] = t;
        }
        __syncthreads();
        #pragma unroll
        for (int i = 0; i < 4; i++) {
            int m = ty * 4 + i;
            float t = tile[m][tx];
            __nv_bfloat16 hi = __float2bfloat16(t);
            size_t o = ((size_t)b * LL + m0 + m) * LL + l0 + tx;
            g_eah[o] = hi;
            g_eal[o] = __float2bfloat16(t - __bfloat162float(hi));
        }
        __syncthreads();
    }
    red[ty][tx] = sum;
    __syncthreads();
    if (ty == 0) {
        float s = 0.f;
        #pragma unroll
        for (int j = 0; j < 8; j++) s += red[j][tx];
        g_ia[b * LL + m0 + tx] = 1.f / s;
    }
}

// ---------------------------------------------------------------------------
// Beta softmax over m per row l: unnormalized exp -> g_ebh/l, 1/sum -> g_ib.
// ---------------------------------------------------------------------------
__global__ __launch_bounds__(256)
void k_softmax_rows(const float* __restrict__ mask2) {
    int row = blockIdx.x;
    int b = row >> 10;
    const float* p = g_e + (size_t)row * LL;
    const float* mk = mask2 + b * LL;
    int tid = threadIdx.x;
    __shared__ float red[256];
    float v[4];
    float mx = -3.4e38f;
    #pragma unroll
    for (int i = 0; i < 4; i++) {
        int m = tid + i * 256;
        v[i] = p[m] * mk[m];
        mx = fmaxf(mx, v[i]);
    }
    red[tid] = mx; __syncthreads();
    for (int s = 128; s > 0; s >>= 1) {
        if (tid < s) red[tid] = fmaxf(red[tid], red[tid + s]);
        __syncthreads();
    }
    mx = red[0]; __syncthreads();
    float sum = 0.f;
    #pragma unroll
    for (int i = 0; i < 4; i++) { v[i] = __expf(v[i] - mx); sum += v[i]; }
    red[tid] = sum; __syncthreads();
    for (int s = 128; s > 0; s >>= 1) {
        if (tid < s) red[tid] += red[tid + s];
        __syncthreads();
    }
    float total = red[0];
    #pragma unroll
    for (int i = 0; i < 4; i++) {
        int m = tid + i * 256;
        __nv_bfloat16 hi = __float2bfloat16(v[i]);
        g_ebh[(size_t)row * LL + m] = hi;
        g_ebl[(size_t)row * LL + m] = __float2bfloat16(v[i] - __bfloat162float(hi));
    }
    if (tid == 0) g_ib[row] = 1.f / total;
}

// ---------------------------------------------------------------------------
extern "C" void kernel_launch(void* const* d_in, const int* in_sizes, int n_in,
                              void* d_out, int out_size) {
    const float* s1    = (const float*)d_in[0];
    const float* s2    = (const float*)d_in[1];
    const float* mask1 = (const float*)d_in[2];
    const float* mask2 = (const float*)d_in[3];
    const float* W1    = (const float*)d_in[4];
    const float* b1    = (const float*)d_in[5];
    const float* W2    = (const float*)d_in[6];
    const float* b2    = (const float*)d_in[7];
    float* out       = (float*)d_out;
    float* out_alpha = out;
    float* out_beta  = out + (size_t)NB*LL*NI;

    float *p_e, *p_ia, *p_ib;
    __nv_bfloat16 *p_tph, *p_tpl, *p_h1h, *p_h1l, *p_h2h, *p_h2l;
    __nv_bfloat16 *p_eah, *p_eal, *p_ebh, *p_ebl;
    __nv_bfloat16 *p_s1h, *p_s1l, *p_s2h, *p_s2l;
    __nv_bfloat16 *p_s1ph, *p_s1pl, *p_s2ph, *p_s2pl;
    __nv_bfloat16 *p_w1th, *p_w1tl, *p_w2th, *p_w2tl;
    cudaGetSymbolAddress((void**)&p_e,    g_e);
    cudaGetSymbolAddress((void**)&p_ia,   g_ia);
    cudaGetSymbolAddress((void**)&p_ib,   g_ib);
    cudaGetSymbolAddress((void**)&p_tph,  g_tph);
    cudaGetSymbolAddress((void**)&p_tpl,  g_tpl);
    cudaGetSymbolAddress((void**)&p_h1h,  g_h1h);
    cudaGetSymbolAddress((void**)&p_h1l,  g_h1l);
    cudaGetSymbolAddress((void**)&p_h2h,  g_h2h);
    cudaGetSymbolAddress((void**)&p_h2l,  g_h2l);
    cudaGetSymbolAddress((void**)&p_eah,  g_eah);
    cudaGetSymbolAddress((void**)&p_eal,  g_eal);
    cudaGetSymbolAddress((void**)&p_ebh,  g_ebh);
    cudaGetSymbolAddress((void**)&p_ebl,  g_ebl);
    cudaGetSymbolAddress((void**)&p_s1h,  g_s1h);
    cudaGetSymbolAddress((void**)&p_s1l,  g_s1l);
    cudaGetSymbolAddress((void**)&p_s2h,  g_s2h);
    cudaGetSymbolAddress((void**)&p_s2l,  g_s2l);
    cudaGetSymbolAddress((void**)&p_s1ph, g_s1ph);
    cudaGetSymbolAddress((void**)&p_s1pl, g_s1pl);
    cudaGetSymbolAddress((void**)&p_s2ph, g_s2ph);
    cudaGetSymbolAddress((void**)&p_s2pl, g_s2pl);
    cudaGetSymbolAddress((void**)&p_w1th, g_w1th);
    cudaGetSymbolAddress((void**)&p_w1tl, g_w1tl);
    cudaGetSymbolAddress((void**)&p_w2th, g_w2th);
    cudaGetSymbolAddress((void**)&p_w2tl, g_w2tl);

    const int MMA_SMEM = 2 * BUFB;   // 81920
    cudaFuncSetAttribute(gemm_mma<0>, cudaFuncAttributeMaxDynamicSharedMemorySize, MMA_SMEM);
    cudaFuncSetAttribute(gemm_mma<1>, cudaFuncAttributeMaxDynamicSharedMemorySize, MMA_SMEM);
    cudaFuncSetAttribute(gemm_mma<2>, cudaFuncAttributeMaxDynamicSharedMemorySize, MMA_SMEM);

    dim3 blk(256);

    // 1-2: W1^T, W2^T splits (tiny)
    k_wsplit<<<dim3(DP/32, 256/32), blk>>>(W1, p_w1th, p_w1tl, NI, NH, DP);
    k_wsplit<<<dim3(KH/32, 256/32), blk>>>(W2, p_w2th, p_w2tl, NH, NH, KH);

    // 3-4: s splits (transposed for beta/alpha B, natural for MLP A)
    {
        dim3 gt(LL / 32, DP / 32, NB);
        k_split_transpose<<<gt, blk>>>(s1, p_s1h, p_s1l, p_s1ph, p_s1pl);
        k_split_transpose<<<gt, blk>>>(s2, p_s2h, p_s2l, p_s2ph, p_s2pl);
    }

    // 5-8: MLP on tensor cores (effective K=608 then K=224), bf16-pair outputs
    {
        dim3 g1(2, NR / 128, 1);   // N=256 padded
        gemm_mma<1><<<g1, blk, MMA_SMEM>>>(p_s1ph, p_s1pl, p_w1th, p_w1tl,
                                           b1, nullptr, nullptr, p_tph, p_tpl,
                                           DPE, DP, DP, KH, NH, 0, 0, 0);
        gemm_mma<1><<<g1, blk, MMA_SMEM>>>(p_tph, p_tpl, p_w2th, p_w2tl,
                                           b2, nullptr, nullptr, p_h1h, p_h1l,
                                           KHE, KH, KH, KH, NH, 0, 0, 0);
        gemm_mma<1><<<g1, blk, MMA_SMEM>>>(p_s2ph, p_s2pl, p_w1th, p_w1tl,
                                           b1, nullptr, nullptr, p_tph, p_tpl,
                                           DPE, DP, DP, KH, NH, 0, 0, 0);
        gemm_mma<1><<<g1, blk, MMA_SMEM>>>(p_tph, p_tpl, p_w2th, p_w2tl,
                                           b2, nullptr, nullptr, p_h2h, p_h2l,
                                           KHE, KH, KH, KH, NH, 0, 0, 0);
    }

    // 9: e[b,l,m] = h1 . h2 (effective K=224)
    {
        dim3 ge(LL / 128, LL / 128, NB);
        gemm_mma<0><<<ge, blk, MMA_SMEM>>>(p_h1h, p_h1l, p_h2h, p_h2l,
                                           nullptr, nullptr, p_e, nullptr, nullptr,
                                           KHE, KH, KH, LL, LL,
                                           (size_t)LL*KH, (size_t)LL*KH, (size_t)LL*LL);
    }

    // 10-11: softmaxes
    {
        dim3 gs(LL / 32, NB);
        k_softmax_cols<<<gs, blk>>>(mask1);
    }
    k_softmax_rows<<<NR, blk>>>(mask2);

    // 12-13: alphas / betas
    {
        dim3 ga(DP / 128, LL / 128, NB);
        gemm_mma<2><<<ga, blk, MMA_SMEM>>>(p_eah, p_eal, p_s1h, p_s1l,
                                           p_ia, mask2, out_alpha, nullptr, nullptr,
                                           LL, LL, LL, NI, NI,
                                           (size_t)LL*LL, (size_t)DP*LL, (size_t)LL*NI);
        gemm_mma<2><<<ga, blk, MMA_SMEM>>>(p_ebh, p_ebl, p_s2h, p_s2l,
                                           p_ib, mask1, out_beta, nullptr, nullptr,
                                           LL, LL, LL, NI, NI,
                                           (size_t)LL*LL, (size_t)DP*LL, (size_t)LL*NI);
    }
}